// round 11
// baseline (speedup 1.0000x reference)
#include <cuda_runtime.h>
#include <cuda_bf16.h>

// ---------------------------------------------------------------------------
// LocalAttention: x[8,128,128,128] --1x1 convs(W1,W2,W3:[64,128])--> q,k,v
// --9x9 dilated(2) local attention--> out[8,64,128,128], all fp32.
//
// Parity trick: dilation-2 only mixes same-parity pixels; 4 interleaved 64x64
// subgrids with dense 9x9 neighborhoods. K/V live in zero-padded 72x72 planes
// (borders stay zero: __device__ globals are zero-initialized; only interiors
// are written), so the attention kernel needs no bounds checks.
//
// v6.1: conv = round-7 (LDG weights, 3 CTAs/SM). Attention = round-5
// structure (smem-staged K/V, warp-per-px-row S, lazy softmax, conflict-free
// O) on an 8x16 pixel tile per CTA (512 threads): K halo 384 pos serves
// 128 px (3.0 pos-loads/px vs 4.0) -> -25% staging traffic; barriers/prologs
// per pixel halved. smem 176.5KB, 1 CTA/SM, 16 warps.
// (Round-10 fix: V staging trip count 6144 float4, not 6528 — the 68-float
// PITCH leaked into the count; OOB pos up to 407 caused the illegal access.)
// ---------------------------------------------------------------------------

#define NIMG 8
#define CIN  128
#define COUT 64
#define HW   128
#define NSUB 32              // 8 images * 4 parities
#define PADD 72              // 64 + 2*4 halo
#define PPLANE (PADD*PADD)   // 5184

// scratch (device-global; zero-initialized at module load)
__device__ __align__(16) float g_Q[(size_t)NSUB * 64 * 4096];   // [sub][c][sy*64+sx]
__device__ __align__(16) float g_K[(size_t)NSUB * 64 * PPLANE]; // [sub][c][(sy+4)*72+(sx+4)]
__device__ __align__(16) float g_V[(size_t)NSUB * PPLANE * 64]; // [sub][(sy+4)*72+(sx+4)][c]
__device__ __align__(16) float g_Wt[128 * 192];                 // [c][o] o:0-63 W1|64-127 W2|128-191 W3

// ---- packed f32x2 helpers --------------------------------------------------
typedef unsigned long long u64;

__device__ __forceinline__ u64 pk2(float a, float b) {
    u64 r; asm("mov.b64 %0, {%1, %2};" : "=l"(r) : "f"(a), "f"(b)); return r;
}
__device__ __forceinline__ void up2(u64 v, float& a, float& b) {
    asm("mov.b64 {%0, %1}, %2;" : "=f"(a), "=f"(b) : "l"(v));
}
__device__ __forceinline__ void fma2(u64& d, u64 a, u64 b) {
    asm("fma.rn.f32x2 %0, %1, %2, %3;" : "=l"(d) : "l"(a), "l"(b), "l"(d));
}
__device__ __forceinline__ void lds2(u64& a, u64& b, const float* p) {
    unsigned sp = (unsigned)__cvta_generic_to_shared(p);
    asm volatile("ld.shared.v2.b64 {%0, %1}, [%2];" : "=l"(a), "=l"(b) : "r"(sp));
}
__device__ __forceinline__ u64 lds1(const float* p) {
    u64 a; unsigned sp = (unsigned)__cvta_generic_to_shared(p);
    asm volatile("ld.shared.b64 %0, [%1];" : "=l"(a) : "r"(sp));
    return a;
}

// ---------------------------------------------------------------------------
// Kernel 0: transpose weights -> g_Wt[c][o]  (tiny)
// ---------------------------------------------------------------------------
__global__ void wt_kernel(const float* __restrict__ W1,
                          const float* __restrict__ W2,
                          const float* __restrict__ W3)
{
    int i = blockIdx.x * 256 + threadIdx.x;     // 24576 total
    if (i >= 192 * 128) return;
    int o = i >> 7, c = i & 127;
    const float* Wt = (o < 64) ? W1 : ((o < 128) ? W2 : W3);
    g_Wt[c * 192 + o] = Wt[(o & 63) * 128 + c];
}

// ---------------------------------------------------------------------------
// Kernel 1: fused 1x1 convs.  CTA = (wh, h, n): 64-px half row x 192 oc.
// smem: xs[128c][64w] = 32KB only; W read via warp-uniform LDG (L1-resident).
// Thread (w_t=tid%16 -> 4w, oc_t=tid/16 -> 12oc). 3 CTAs/SM.
// ---------------------------------------------------------------------------
#define CONV_SMEM_FLOATS 8192
__global__ __launch_bounds__(256, 3) void conv_kernel(
    const float* __restrict__ x)
{
    extern __shared__ float sm[];
    float* xs = sm;                 // [128][64]

    const int tid = threadIdx.x;
    const int wh  = blockIdx.x;     // 0/1 half of the row
    const int h   = blockIdx.y;
    const int n   = blockIdx.z;
    const int w0  = wh * 64;
    const int w_t = tid & 15;
    const int oc_t = tid >> 4;

    const float* xbase = x + ((size_t)n * CIN) * HW * HW + (size_t)h * HW + w0;
    #pragma unroll
    for (int it = 0; it < 8; it++) {
        int i = it * 256 + tid;                 // 2048 float4
        int c = i >> 4, w4 = (i & 15) << 2;
        *(float4*)&xs[c * 64 + w4] =
            *(const float4*)(xbase + (size_t)c * HW * HW + w4);
    }
    __syncthreads();

    u64 acc[12][2];
    #pragma unroll
    for (int j = 0; j < 12; j++) { acc[j][0] = 0ull; acc[j][1] = 0ull; }

    const float* wrow = g_Wt + 12 * oc_t;
    #pragma unroll 4
    for (int c = 0; c < 128; c++) {
        u64 xp0, xp1;
        lds2(xp0, xp1, &xs[c * 64 + 4 * w_t]);
        const float4 wa = __ldg((const float4*)(wrow + c * 192));
        const float4 wb = __ldg((const float4*)(wrow + c * 192 + 4));
        const float4 wc = __ldg((const float4*)(wrow + c * 192 + 8));
        float wv[12] = {wa.x, wa.y, wa.z, wa.w, wb.x, wb.y, wb.z, wb.w,
                        wc.x, wc.y, wc.z, wc.w};
        #pragma unroll
        for (int j = 0; j < 12; j++) {
            u64 s = pk2(wv[j], wv[j]);
            fma2(acc[j][0], s, xp0);
            fma2(acc[j][1], s, xp1);
        }
    }

    float ov[12][4];
    #pragma unroll
    for (int j = 0; j < 12; j++) {
        up2(acc[j][0], ov[j][0], ov[j][1]);
        up2(acc[j][1], ov[j][2], ov[j][3]);
    }
    const int sy  = h >> 1;
    const int ph2 = (h & 1) * 2;
    const int sub_e = n * 4 + ph2;
    const int sub_o = sub_e + 1;
    const int sx0 = wh * 32 + 2 * w_t;

    #pragma unroll
    for (int j = 0; j < 12; j++) {
        int o = 12 * oc_t + j;
        if (o < 64) {            // Q
            size_t be = ((size_t)(sub_e * 64 + o)) * 4096 + sy * 64 + sx0;
            size_t bo = ((size_t)(sub_o * 64 + o)) * 4096 + sy * 64 + sx0;
            *(float2*)(g_Q + be) = make_float2(ov[j][0], ov[j][2]);
            *(float2*)(g_Q + bo) = make_float2(ov[j][1], ov[j][3]);
        } else if (o < 128) {    // K
            int oc = o - 64;
            size_t be = ((size_t)(sub_e * 64 + oc)) * PPLANE + (sy + 4) * PADD + 4 + sx0;
            size_t bo = ((size_t)(sub_o * 64 + oc)) * PPLANE + (sy + 4) * PADD + 4 + sx0;
            *(float2*)(g_K + be) = make_float2(ov[j][0], ov[j][2]);
            *(float2*)(g_K + bo) = make_float2(ov[j][1], ov[j][3]);
        }
    }

    __syncthreads();           // xs reads done; reuse as vsm[64 w][68]
    float* vsm = sm;
    #pragma unroll
    for (int j = 0; j < 12; j++) {
        int o = 12 * oc_t + j;
        if (o >= 128) {
            int oc = o - 128;
            #pragma unroll
            for (int jj = 0; jj < 4; jj++)
                vsm[(4 * w_t + jj) * 68 + oc] = ov[j][jj];
        }
    }
    __syncthreads();
    #pragma unroll
    for (int it = 0; it < 4; it++) {
        int i = it * 256 + tid;                 // 1024 float4: (wl 64, c4 16)
        int c4 = i & 15, wl = i >> 4;
        float4 v = *(float4*)&vsm[wl * 68 + c4 * 4];
        int w = w0 + wl;
        int pw = w & 1, sx = w >> 1;
        int sub = n * 4 + ph2 + pw;
        size_t a = ((size_t)sub * PPLANE + (sy + 4) * PADD + sx + 4) * 64 + c4 * 4;
        *(float4*)(g_V + a) = v;
    }
}

// ---------------------------------------------------------------------------
// Kernel 2: local attention, 8(w)x16(h) pixel tile per CTA, 512 threads,
// 1 CTA/SM (16 warps).
// smem (floats):
//   phase 1: Ks [64c][384pos] @ 0 (24576), Qs [64c][128px] @ 24576 (8192)
//   phase 2: P  [128px][148]  @ 0 (18944), sums[128] @ 18944,
//            Vs [384pos][68]  @ 19072 (26112)  -> peak 45184 fl = 176.5KB
//   phase 3: O  [128px][68]   @ 0 (overlays P after all P reads)
// ---------------------------------------------------------------------------
#define OFF_K   0
#define KPITCH  384
#define OFF_Q   24576
#define OFF_P   0
#define PP      148
#define OFF_SUM 18944
#define OFF_V   19072
#define OFF_O   0
#define ATTN_SMEM_FLOATS 45184

__global__ __launch_bounds__(512, 1) void attn_kernel(float* __restrict__ out)
{
    extern __shared__ float sm[];
    const int tid  = threadIdx.x;
    const int lane = tid & 31;
    const int tile = blockIdx.x;          // 0..31 : (byy 0..3) x (bx 0..7)
    const int sub  = blockIdx.y;          // 0..31
    const int byy = tile >> 3, bx = tile & 7;

    // ---- load Q [64c][128px] ----------------------------------------------
    #pragma unroll
    for (int it = 0; it < 4; it++) {
        int i = it * 512 + tid;           // 2048 float4: (c 64, ty 16, f4 2)
        int f4 = i & 1, ty = (i >> 1) & 15, c = i >> 5;
        const float* src = g_Q + ((size_t)(sub * 64 + c)) * 4096
                         + (byy * 16 + ty) * 64 + bx * 8 + f4 * 4;
        *(float4*)&sm[OFF_Q + c * 128 + ty * 8 + f4 * 4] = *(const float4*)src;
    }
    // ---- load K [64c][384pos], pos = hy*16+hx, hy 0..23 --------------------
    #pragma unroll
    for (int it = 0; it < 12; it++) {
        int i = it * 512 + tid;           // 6144 float4
        int hx4 = i & 3;
        int t   = i >> 2;                 // 0..1535 = (c 64, hy 24)
        int c   = (t * 2731) >> 16;       // t / 24 for t < 1536
        int hy  = t - c * 24;
        const float* src = g_K + ((size_t)(sub * 64 + c)) * PPLANE
                         + (byy * 16 + hy) * PADD + bx * 8 + hx4 * 4;
        *(float4*)&sm[OFF_K + c * KPITCH + hy * 16 + hx4 * 4] = *(const float4*)src;
    }
    __syncthreads();

    // ---- S = Q.K^T over the 9 valid halo rows ------------------------------
    // warp = query row ty (0..15); lanes cover rows ty..ty+7 (128 pos, pairs)
    // plus row ty+8 (16 pos, lanes 0..7 useful; others dup via &7).
    const int ty  = tid >> 5;
    const int tx4 = lane * 4;
    u64 acc[8][2], accx[8];
    #pragma unroll
    for (int p = 0; p < 8; p++) { acc[p][0] = 0ull; acc[p][1] = 0ull; accx[p] = 0ull; }

    const int kmain = OFF_K + ty * 16 + tx4;
    const int kxoff = OFF_K + (ty + 8) * 16 + 2 * (lane & 7);

    #pragma unroll 4
    for (int c = 0; c < 64; c++) {
        float4 qa = *(const float4*)&sm[OFF_Q + c * 128 + ty * 8];
        float4 qb = *(const float4*)&sm[OFF_Q + c * 128 + ty * 8 + 4];
        u64 kp0, kp1;
        lds2(kp0, kp1, &sm[kmain + c * KPITCH]);
        u64 kx = lds1(&sm[kxoff + c * KPITCH]);
        float qv[8] = {qa.x, qa.y, qa.z, qa.w, qb.x, qb.y, qb.z, qb.w};
        #pragma unroll
        for (int p = 0; p < 8; p++) {
            u64 qs = pk2(qv[p], qv[p]);
            fma2(acc[p][0], qs, kp0);
            fma2(acc[p][1], qs, kp1);
            fma2(accx[p],  qs, kx);
        }
    }

    // ---- mask + lazy softmax (exp + 1/sum; scale at end) -------------------
    float s[8][4], sx[8][2], inv[8];
    #pragma unroll
    for (int p = 0; p < 8; p++) {
        up2(acc[p][0], s[p][0], s[p][1]);
        up2(acc[p][1], s[p][2], s[p][3]);
        up2(accx[p],   sx[p][0], sx[p][1]);
    }
    #pragma unroll
    for (int p = 0; p < 8; p++) {
        #pragma unroll
        for (int k = 0; k < 4; k++) {
            int hx = (tx4 + k) & 15;
            if ((unsigned)(hx - p) > 8u) s[p][k] = -1e30f;
        }
        #pragma unroll
        for (int j = 0; j < 2; j++) {
            int hx = 2 * (lane & 7) + j;
            if ((unsigned)(hx - p) > 8u) sx[p][j] = -1e30f;
        }
        float m = fmaxf(fmaxf(s[p][0], s[p][1]), fmaxf(s[p][2], s[p][3]));
        if (lane < 8) m = fmaxf(m, fmaxf(sx[p][0], sx[p][1]));
        #pragma unroll
        for (int k = 16; k >= 1; k >>= 1)
            m = fmaxf(m, __shfl_xor_sync(0xffffffffu, m, k));
        float sum = 0.f;
        #pragma unroll
        for (int k = 0; k < 4; k++) { s[p][k] = __expf(s[p][k] - m); sum += s[p][k]; }
        sx[p][0] = __expf(sx[p][0] - m);
        sx[p][1] = __expf(sx[p][1] - m);
        if (lane < 8) sum += sx[p][0] + sx[p][1];
        #pragma unroll
        for (int k = 16; k >= 1; k >>= 1)
            sum += __shfl_xor_sync(0xffffffffu, sum, k);
        inv[p] = __fdividef(1.f, sum);
    }

    __syncthreads();   // all K/Q reads done; safe to overlay P and load V

    // ---- store compact P (unnormalized exp) + 1/sums -----------------------
    #pragma unroll
    for (int p = 0; p < 8; p++) {
        int px = ty * 8 + p;
        *(float4*)&sm[OFF_P + px * PP + tx4] =
            make_float4(s[p][0], s[p][1], s[p][2], s[p][3]);
        if (lane < 8)
            *(float2*)&sm[OFF_P + px * PP + 128 + 2 * lane] =
                make_float2(sx[p][0], sx[p][1]);
        if (lane == 0) sm[OFF_SUM + px] = inv[p];
    }
    // ---- load V [384pos][68] (overlays old K/Q space region) ---------------
    #pragma unroll
    for (int it = 0; it < 12; it++) {
        int i = it * 512 + tid;           // 6144 float4: (pos 384, c4 16)
        int c4 = i & 15, pos = i >> 4;
        int hy = pos >> 4, hx = pos & 15;
        const float* src = g_V + ((size_t)sub * PPLANE
                         + (byy * 16 + hy) * PADD + bx * 8 + hx) * 64 + c4 * 4;
        *(float4*)&sm[OFF_V + pos * 68 + c4 * 4] = *(const float4*)src;
    }
    __syncthreads();

    // ---- O = P.V over 144 positions: thread = 2px x 8ch --------------------
    const int c_t = tid & 7;
    const int pxo = tid >> 3;             // 0..63 ; warp covers one px row
    const int px0 = 2 * pxo;
    const int oty = px0 >> 3;             // == own warp's ty
    u64 oacc[2][4];
    #pragma unroll
    for (int i = 0; i < 2; i++)
        #pragma unroll
        for (int j = 0; j < 4; j++) oacc[i][j] = 0ull;

    const float* Pr0 = &sm[OFF_P + px0 * PP];
    const float* Pr1 = &sm[OFF_P + (px0 + 1) * PP];

    #pragma unroll 3
    for (int r = 0; r < 9; r++) {
        const float* Vr = &sm[OFF_V + ((oty + r) * 16) * 68 + c_t * 8];
        const int pb = r * 16;
        #pragma unroll
        for (int hx = 0; hx < 16; hx++) {
            float p0 = Pr0[pb + hx];
            float p1 = Pr1[pb + hx];
            u64 pp0 = pk2(p0, p0), pp1 = pk2(p1, p1);
            u64 v0, v1, v2, v3;
            lds2(v0, v1, Vr + hx * 68);
            lds2(v2, v3, Vr + hx * 68 + 4);
            fma2(oacc[0][0], pp0, v0); fma2(oacc[0][1], pp0, v1);
            fma2(oacc[0][2], pp0, v2); fma2(oacc[0][3], pp0, v3);
            fma2(oacc[1][0], pp1, v0); fma2(oacc[1][1], pp1, v1);
            fma2(oacc[1][2], pp1, v2); fma2(oacc[1][3], pp1, v3);
        }
    }

    // this thread's 1/sums come from its own warp's registers (p = 2*(pxo&3))
    const int sel = pxo & 3;
    float iv0 = (sel == 0) ? inv[0] : (sel == 1) ? inv[2] : (sel == 2) ? inv[4] : inv[6];
    float iv1 = (sel == 0) ? inv[1] : (sel == 1) ? inv[3] : (sel == 2) ? inv[5] : inv[7];

    __syncthreads();   // ALL P reads done; safe to overlay O staging onto P

    #pragma unroll
    for (int j = 0; j < 2; j++) {
        int px = px0 + j;
        float iv = j ? iv1 : iv0;
        float f[8];
        up2(oacc[j][0], f[0], f[1]); up2(oacc[j][1], f[2], f[3]);
        up2(oacc[j][2], f[4], f[5]); up2(oacc[j][3], f[6], f[7]);
        #pragma unroll
        for (int k = 0; k < 8; k++) f[k] *= iv;
        *(float4*)&sm[OFF_O + px * 68 + c_t * 8]     = make_float4(f[0], f[1], f[2], f[3]);
        *(float4*)&sm[OFF_O + px * 68 + c_t * 8 + 4] = make_float4(f[4], f[5], f[6], f[7]);
    }
    __syncthreads();

    // ---- store to out ------------------------------------------------------
    const int n  = sub >> 2;
    const int ph = (sub >> 1) & 1;
    const int pw = sub & 1;
    #pragma unroll
    for (int it = 0; it < 16; it++) {
        int i = it * 512 + tid;           // 8192: (tyy 16, c 64, tx 8)
        int tx = i & 7, c = (i >> 3) & 63, tyy = i >> 9;
        float val = sm[OFF_O + (tyy * 8 + tx) * 68 + c];
        int hh = 2 * (byy * 16 + tyy) + ph;
        int ww = 2 * (bx * 8 + tx) + pw;
        out[((size_t)(n * 64 + c)) * (HW * HW) + hh * HW + ww] = val;
    }
}

// ---------------------------------------------------------------------------
extern "C" void kernel_launch(void* const* d_in, const int* in_sizes, int n_in,
                              void* d_out, int out_size) {
    const float* x  = (const float*)d_in[0];
    const float* W1 = (const float*)d_in[1];
    const float* W2 = (const float*)d_in[2];
    const float* W3 = (const float*)d_in[3];
    float* out = (float*)d_out;
    (void)in_sizes; (void)n_in; (void)out_size;

    // 176.5KB dynamic smem > 48KB default: opt-in attribute is REQUIRED.
    cudaFuncSetAttribute(attn_kernel, cudaFuncAttributeMaxDynamicSharedMemorySize,
                         ATTN_SMEM_FLOATS * 4);

    // 0) transpose weights into g_Wt[c][o]
    wt_kernel<<<96, 256>>>(W1, W2, W3);
    // 1) fused 1x1 convs (K/V borders stay zero from static zero-init)
    conv_kernel<<<dim3(2, HW, NIMG), 256, CONV_SMEM_FLOATS * 4>>>(x);
    // 2) local attention (8x16 tile per CTA)
    attn_kernel<<<dim3(32, NSUB), 512, ATTN_SMEM_FLOATS * 4>>>(out);
}

// round 14
// speedup vs baseline: 1.4447x; 1.4447x over previous
#include <cuda_runtime.h>
#include <cuda_fp16.h>

#define NIMG 8
#define CIN  128
#define HW   128
#define NSUB 32
#define PADD 72
#define PPLANE (PADD*PADD)

// channel-last fp16 hi/lo globals (zero-init -> padded borders are 0)
__device__ __align__(16) __half g_Qhi[(size_t)NSUB * 4096 * 64];
__device__ __align__(16) __half g_Qlo[(size_t)NSUB * 4096 * 64];
__device__ __align__(16) __half g_Khi[(size_t)NSUB * PPLANE * 64];
__device__ __align__(16) __half g_Klo[(size_t)NSUB * PPLANE * 64];
__device__ __align__(16) __half g_Vhi[(size_t)NSUB * PPLANE * 64];
__device__ __align__(16) __half g_Vlo[(size_t)NSUB * PPLANE * 64];
__device__ __align__(16) float  g_Wt[128 * 192];

typedef unsigned long long u64;
typedef unsigned u32;

__device__ __forceinline__ u64 pk2(float a, float b) {
    u64 r; asm("mov.b64 %0, {%1, %2};" : "=l"(r) : "f"(a), "f"(b)); return r;
}
__device__ __forceinline__ void up2(u64 v, float& a, float& b) {
    asm("mov.b64 {%0, %1}, %2;" : "=f"(a), "=f"(b) : "l"(v));
}
__device__ __forceinline__ void fma2(u64& d, u64 a, u64 b) {
    asm("fma.rn.f32x2 %0, %1, %2, %3;" : "=l"(d) : "l"(a), "l"(b), "l"(d));
}
__device__ __forceinline__ void lds2(u64& a, u64& b, const float* p) {
    unsigned sp = (unsigned)__cvta_generic_to_shared(p);
    asm volatile("ld.shared.v2.b64 {%0, %1}, [%2];" : "=l"(a), "=l"(b) : "r"(sp));
}
__device__ __forceinline__ u32 smem_u32(const void* p) {
    u32 a;
    asm("{ .reg .u64 t; cvta.to.shared.u64 t, %1; cvt.u32.u64 %0, t; }" : "=r"(a) : "l"(p));
    return a;
}
__device__ __forceinline__ void ldsm4(u32* r, u32 a) {
    asm volatile("ldmatrix.sync.aligned.m8n8.x4.shared.b16 {%0,%1,%2,%3}, [%4];"
        : "=r"(r[0]), "=r"(r[1]), "=r"(r[2]), "=r"(r[3]) : "r"(a));
}
__device__ __forceinline__ void ldsm4t(u32* r, u32 a) {
    asm volatile("ldmatrix.sync.aligned.m8n8.x4.trans.shared.b16 {%0,%1,%2,%3}, [%4];"
        : "=r"(r[0]), "=r"(r[1]), "=r"(r[2]), "=r"(r[3]) : "r"(a));
}
__device__ __forceinline__ void mma16816(float* d, const u32* a, u32 b0, u32 b1) {
    asm volatile("mma.sync.aligned.m16n8k16.row.col.f32.f16.f16.f32 "
        "{%0,%1,%2,%3}, {%4,%5,%6,%7}, {%8,%9}, {%0,%1,%2,%3};"
        : "+f"(d[0]), "+f"(d[1]), "+f"(d[2]), "+f"(d[3])
        : "r"(a[0]), "r"(a[1]), "r"(a[2]), "r"(a[3]), "r"(b0), "r"(b1));
}
__device__ __forceinline__ u32 packh2(float lo, float hi) {
    u32 r; asm("cvt.rn.f16x2.f32 %0, %1, %2;" : "=r"(r) : "f"(hi), "f"(lo));
    return r;
}
__device__ __forceinline__ float hresid(float x) {
    return x - __half2float(__float2half_rn(x));
}

// ---------------------------------------------------------------------------
__global__ void wt_kernel(const float* __restrict__ W1, const float* __restrict__ W2,
                          const float* __restrict__ W3)
{
    int i = blockIdx.x * 256 + threadIdx.x;
    if (i >= 192 * 128) return;
    int o = i >> 7, c = i & 127;
    const float* Wt = (o < 64) ? W1 : ((o < 128) ? W2 : W3);
    g_Wt[c * 192 + o] = Wt[(o & 63) * 128 + c];
}

// ---------------------------------------------------------------------------
// conv: round-7 GEMM core; epilogue bounces Q,K,V via smem and stores fp16
// hi/lo channel-last.
// ---------------------------------------------------------------------------
#define CONV_SMEM_FLOATS 8192
__global__ __launch_bounds__(256, 3) void conv_kernel(const float* __restrict__ x)
{
    extern __shared__ float sm[];
    float* xs = sm;
    const int tid = threadIdx.x;
    const int wh = blockIdx.x, h = blockIdx.y, n = blockIdx.z;
    const int w0 = wh * 64, w_t = tid & 15, oc_t = tid >> 4;

    const float* xbase = x + ((size_t)n * CIN) * HW * HW + (size_t)h * HW + w0;
    #pragma unroll
    for (int it = 0; it < 8; it++) {
        int i = it * 256 + tid;
        int c = i >> 4, w4 = (i & 15) << 2;
        *(float4*)&xs[c * 64 + w4] = *(const float4*)(xbase + (size_t)c * HW * HW + w4);
    }
    __syncthreads();

    u64 acc[12][2];
    #pragma unroll
    for (int j = 0; j < 12; j++) { acc[j][0] = 0ull; acc[j][1] = 0ull; }
    const float* wrow = g_Wt + 12 * oc_t;
    #pragma unroll 4
    for (int c = 0; c < 128; c++) {
        u64 xp0, xp1;
        lds2(xp0, xp1, &xs[c * 64 + 4 * w_t]);
        const float4 wa = __ldg((const float4*)(wrow + c * 192));
        const float4 wb = __ldg((const float4*)(wrow + c * 192 + 4));
        const float4 wc = __ldg((const float4*)(wrow + c * 192 + 8));
        float wv[12] = {wa.x, wa.y, wa.z, wa.w, wb.x, wb.y, wb.z, wb.w,
                        wc.x, wc.y, wc.z, wc.w};
        #pragma unroll
        for (int j = 0; j < 12; j++) {
            u64 s = pk2(wv[j], wv[j]);
            fma2(acc[j][0], s, xp0);
            fma2(acc[j][1], s, xp1);
        }
    }
    float ov[12][4];
    #pragma unroll
    for (int j = 0; j < 12; j++) {
        up2(acc[j][0], ov[j][0], ov[j][1]);
        up2(acc[j][1], ov[j][2], ov[j][3]);
    }

    const int sy = h >> 1, ph2 = (h & 1) * 2;
    float* vsm = sm;
    #pragma unroll 1
    for (int rnd = 0; rnd < 3; rnd++) {
        __syncthreads();
        #pragma unroll
        for (int j = 0; j < 12; j++) {
            int o = 12 * oc_t + j;
            if ((o >> 6) == rnd) {
                int oc = o & 63;
                #pragma unroll
                for (int jj = 0; jj < 4; jj++)
                    vsm[(4 * w_t + jj) * 68 + oc] = ov[j][jj];
            }
        }
        __syncthreads();
        #pragma unroll
        for (int it = 0; it < 4; it++) {
            int i = it * 256 + tid;           // (wl 64, c4 16)
            int c4 = i & 15, wl = i >> 4;
            float4 v = *(float4*)&vsm[wl * 68 + c4 * 4];
            uint2 hi, lo;
            hi.x = packh2(v.x, v.y); hi.y = packh2(v.z, v.w);
            lo.x = packh2(hresid(v.x), hresid(v.y));
            lo.y = packh2(hresid(v.z), hresid(v.w));
            int w = w0 + wl, pw = w & 1, sx = w >> 1;
            int sub = n * 4 + ph2 + pw;
            size_t a;
            __half *ph, *pl;
            if (rnd == 0) {
                a = ((size_t)sub * 4096 + sy * 64 + sx) * 64 + c4 * 4;
                ph = g_Qhi; pl = g_Qlo;
            } else {
                a = ((size_t)sub * PPLANE + (sy + 4) * PADD + sx + 4) * 64 + c4 * 4;
                ph = (rnd == 1) ? g_Khi : g_Vhi;
                pl = (rnd == 1) ? g_Klo : g_Vlo;
            }
            *(uint2*)(ph + a) = hi;
            *(uint2*)(pl + a) = lo;
        }
    }
}

// ---------------------------------------------------------------------------
// attn: mma.sync flash pipeline. 256 thr, 1 CTA/SM, 224KB smem.
// smem: Q [128px][64ch] hi/lo (16KB ea), K/V [384pos][64ch] hi/lo (48KB ea),
// all rows 128B, 16B-chunk XOR swizzle (chunk ^= row&7).
// ---------------------------------------------------------------------------
#define SQ_HI 0
#define SQ_LO 16384
#define SK_HI 32768
#define SK_LO 81920
#define SV_HI 131072
#define SV_LO 180224
#define ASMEM 229376

__global__ __launch_bounds__(256, 1) void attn_kernel(float* __restrict__ out)
{
    extern __shared__ char smc[];
    const u32 sb = smem_u32(smc);
    const int tid = threadIdx.x, lane = tid & 31, w = tid >> 5;
    const int tile = blockIdx.x, sub = blockIdx.y;
    const int byy = tile >> 3, bx = tile & 7;

    // ---- stage Q ----
    #pragma unroll
    for (int it = 0; it < 4; it++) {
        int i = it * 256 + tid;               // (r 128, ck 8)
        int r = i >> 3, ck = i & 7;
        int sy = byy * 16 + (r >> 3), sx = bx * 8 + (r & 7);
        size_t ga = ((size_t)sub * 4096 + sy * 64 + sx) * 64 + ck * 8;
        u32 off = r * 128 + ((ck ^ (r & 7)) << 4);
        *(uint4*)(smc + SQ_HI + off) = *(const uint4*)(g_Qhi + ga);
        *(uint4*)(smc + SQ_LO + off) = *(const uint4*)(g_Qlo + ga);
    }
    // ---- stage K,V ----
    #pragma unroll
    for (int it = 0; it < 12; it++) {
        int i = it * 256 + tid;               // (pos 384, ck 8)
        int pos = i >> 3, ck = i & 7;
        int py = byy * 16 + (pos >> 4), px = bx * 8 + (pos & 15);
        size_t ga = ((size_t)sub * PPLANE + py * PADD + px) * 64 + ck * 8;
        u32 off = pos * 128 + ((ck ^ (pos & 7)) << 4);
        *(uint4*)(smc + SK_HI + off) = *(const uint4*)(g_Khi + ga);
        *(uint4*)(smc + SK_LO + off) = *(const uint4*)(g_Klo + ga);
        *(uint4*)(smc + SV_HI + off) = *(const uint4*)(g_Vhi + ga);
        *(uint4*)(smc + SV_LO + off) = *(const uint4*)(g_Vlo + ga);
    }
    __syncthreads();

    // ---- A fragments: Q rows 16w..16w+15, 4 k-steps ----
    u32 ah[4][4], al[4][4];
    {
        int ar = 16 * w + (lane & 15);
        #pragma unroll
        for (int t = 0; t < 4; t++) {
            u32 ck = 2 * t + (lane >> 4);
            u32 off = ar * 128 + ((ck ^ (ar & 7)) << 4);
            ldsm4(ah[t], sb + SQ_HI + off);
            ldsm4(al[t], sb + SQ_LO + off);
        }
    }

    const int g = lane >> 2, tg = lane & 3;
    float m0 = -1e30f, m1 = -1e30f, s0 = 0.f, s1 = 0.f;
    float o[8][4];
    #pragma unroll
    for (int nb = 0; nb < 8; nb++)
        #pragma unroll
        for (int j = 0; j < 4; j++) o[nb][j] = 0.f;

    const int cb0 = w >> 1;
    #pragma unroll 1
    for (int ci = 0; ci < 3; ci++) {
        const int cb = cb0 + ci;

        // ---- S = Q.K^T over 64-pos chunk ----
        float sacc[8][4];
        #pragma unroll
        for (int nb = 0; nb < 8; nb++)
            #pragma unroll
            for (int j = 0; j < 4; j++) sacc[nb][j] = 0.f;

        #pragma unroll
        for (int t = 0; t < 4; t++) {
            int rb = 64 * cb + ((lane >> 4) << 3) + (lane & 7);
            u32 ck = 2 * t + ((lane >> 3) & 1);
            u32 bh[4][4];
            #pragma unroll
            for (int u = 0; u < 4; u++) {
                int r2 = rb + 16 * u;
                ldsm4(bh[u], sb + SK_HI + r2 * 128 + ((ck ^ (r2 & 7)) << 4));
            }
            #pragma unroll
            for (int nb = 0; nb < 8; nb++) {
                mma16816(sacc[nb], ah[t], bh[nb >> 1][(nb & 1) * 2], bh[nb >> 1][(nb & 1) * 2 + 1]);
                mma16816(sacc[nb], al[t], bh[nb >> 1][(nb & 1) * 2], bh[nb >> 1][(nb & 1) * 2 + 1]);
            }
            #pragma unroll
            for (int u = 0; u < 4; u++) {
                int r2 = rb + 16 * u;
                ldsm4(bh[u], sb + SK_LO + r2 * 128 + ((ck ^ (r2 & 7)) << 4));
            }
            #pragma unroll
            for (int nb = 0; nb < 8; nb++)
                mma16816(sacc[nb], ah[t], bh[nb >> 1][(nb & 1) * 2], bh[nb >> 1][(nb & 1) * 2 + 1]);
        }

        // ---- mask (rows ty=2w,2w+1; cols tx=g) ----
        #pragma unroll
        for (int nb = 0; nb < 8; nb++) {
            int hy = 4 * cb + (nb >> 1);
            int hx0 = (nb & 1) * 8 + tg * 2;
            bool y0 = (unsigned)(hy - 2 * w) <= 8u;
            bool y1 = (unsigned)(hy - 2 * w - 1) <= 8u;
            bool x0 = (unsigned)(hx0 - g) <= 8u;
            bool x1 = (unsigned)(hx0 + 1 - g) <= 8u;
            if (!(y0 && x0)) sacc[nb][0] = -1e30f;
            if (!(y0 && x1)) sacc[nb][1] = -1e30f;
            if (!(y1 && x0)) sacc[nb][2] = -1e30f;
            if (!(y1 && x1)) sacc[nb][3] = -1e30f;
        }

        // ---- running max + rescale ----
        float mn0 = -1e30f, mn1 = -1e30f;
        #pragma unroll
        for (int nb = 0; nb < 8; nb++) {
            mn0 = fmaxf(mn0, fmaxf(sacc[nb][0], sacc[nb][1]));
            mn1 = fmaxf(mn1, fmaxf(sacc[nb][2], sacc[nb][3]));
        }
        mn0 = fmaxf(mn0, __shfl_xor_sync(0xffffffffu, mn0, 1));
        mn0 = fmaxf(mn0, __shfl_xor_sync(0xffffffffu, mn0, 2));
        mn1 = fmaxf(mn1, __shfl_xor_sync(0xffffffffu, mn1, 1));
        mn1 = fmaxf(mn1, __shfl_xor_sync(0xffffffffu, mn1, 2));
        float nm0 = fmaxf(m0, mn0), nm1 = fmaxf(m1, mn1);
        float sc0 = __expf(m0 - nm0), sc1 = __expf(m1 - nm1);
        m0 = nm0; m1 = nm1;
        s0 *= sc0; s1 *= sc1;
        #pragma unroll
        for (int nb = 0; nb < 8; nb++) {
            o[nb][0] *= sc0; o[nb][1] *= sc0;
            o[nb][2] *= sc1; o[nb][3] *= sc1;
        }

        // ---- P = exp(s-m) as A fragments (hi + residual) ----
        u32 pa[4][4], pl[4][4];
        #pragma unroll
        for (int st = 0; st < 4; st++) {
            float q0 = __expf(sacc[2 * st][0] - m0), q1 = __expf(sacc[2 * st][1] - m0);
            float q2 = __expf(sacc[2 * st][2] - m1), q3 = __expf(sacc[2 * st][3] - m1);
            float r0 = __expf(sacc[2 * st + 1][0] - m0), r1 = __expf(sacc[2 * st + 1][1] - m0);
            float r2 = __expf(sacc[2 * st + 1][2] - m1), r3 = __expf(sacc[2 * st + 1][3] - m1);
            s0 += q0 + q1 + r0 + r1;
            s1 += q2 + q3 + r2 + r3;
            pa[st][0] = packh2(q0, q1); pa[st][1] = packh2(q2, q3);
            pa[st][2] = packh2(r0, r1); pa[st][3] = packh2(r2, r3);
            pl[st][0] = packh2(hresid(q0), hresid(q1));
            pl[st][1] = packh2(hresid(q2), hresid(q3));
            pl[st][2] = packh2(hresid(r0), hresid(r1));
            pl[st][3] = packh2(hresid(r2), hresid(r3));
        }

        // ---- O += P.V ----
        #pragma unroll
        for (int st = 0; st < 4; st++) {
            int row = 64 * cb + 16 * st + ((lane >> 3) & 1) * 8 + (lane & 7);
            u32 bv[4][4];
            #pragma unroll
            for (int q = 0; q < 4; q++) {
                u32 ck = 2 * q + (lane >> 4);
                ldsm4t(bv[q], sb + SV_HI + row * 128 + ((ck ^ (row & 7)) << 4));
            }
            #pragma unroll
            for (int nb = 0; nb < 8; nb++) {
                mma16816(o[nb], pa[st], bv[nb >> 1][(nb & 1) * 2], bv[nb >> 1][(nb & 1) * 2 + 1]);
                mma16816(o[nb], pl[st], bv[nb >> 1][(nb & 1) * 2], bv[nb >> 1][(nb & 1) * 2 + 1]);
            }
            #pragma unroll
            for (int q = 0; q < 4; q++) {
                u32 ck = 2 * q + (lane >> 4);
                ldsm4t(bv[q], sb + SV_LO + row * 128 + ((ck ^ (row & 7)) << 4));
            }
            #pragma unroll
            for (int nb = 0; nb < 8; nb++)
                mma16816(o[nb], pa[st], bv[nb >> 1][(nb & 1) * 2], bv[nb >> 1][(nb & 1) * 2 + 1]);
        }
    }

    // ---- normalize ----
    s0 += __shfl_xor_sync(0xffffffffu, s0, 1);
    s0 += __shfl_xor_sync(0xffffffffu, s0, 2);
    s1 += __shfl_xor_sync(0xffffffffu, s1, 1);
    s1 += __shfl_xor_sync(0xffffffffu, s1, 2);
    float i0 = __fdividef(1.f, s0), i1 = __fdividef(1.f, s1);
    #pragma unroll
    for (int nb = 0; nb < 8; nb++) {
        o[nb][0] *= i0; o[nb][1] *= i0;
        o[nb][2] *= i1; o[nb][3] *= i1;
    }

    __syncthreads();                      // all smem operand reads done
    float* ob = (float*)smc;              // [128px][68] f32 bounce
    {
        int r0 = 16 * w + g, r1 = r0 + 8;
        #pragma unroll
        for (int nb = 0; nb < 8; nb++) {
            *(float2*)&ob[r0 * 68 + 8 * nb + tg * 2] = make_float2(o[nb][0], o[nb][1]);
            *(float2*)&ob[r1 * 68 + 8 * nb + tg * 2] = make_float2(o[nb][2], o[nb][3]);
        }
    }
    __syncthreads();

    const int nimg = sub >> 2;
    const int ph = (sub >> 1) & 1;
    const int pw = sub & 1;
    #pragma unroll
    for (int it = 0; it < 32; it++) {
        int i = it * 256 + tid;           // (tyy 16, c 64, txx 8)
        int txx = i & 7, c = (i >> 3) & 63, tyy = i >> 9;
        float val = ob[(tyy * 8 + txx) * 68 + c];
        int hh = 2 * (byy * 16 + tyy) + ph;
        int ww = 2 * (bx * 8 + txx) + pw;
        out[((size_t)(nimg * 64 + c)) * (HW * HW) + hh * HW + ww] = val;
    }
}

// ---------------------------------------------------------------------------
extern "C" void kernel_launch(void* const* d_in, const int* in_sizes, int n_in,
                              void* d_out, int out_size) {
    const float* x  = (const float*)d_in[0];
    const float* W1 = (const float*)d_in[1];
    const float* W2 = (const float*)d_in[2];
    const float* W3 = (const float*)d_in[3];
    float* out = (float*)d_out;
    (void)in_sizes; (void)n_in; (void)out_size;

    cudaFuncSetAttribute(attn_kernel, cudaFuncAttributeMaxDynamicSharedMemorySize,
                         ASMEM);

    wt_kernel<<<96, 256>>>(W1, W2, W3);
    conv_kernel<<<dim3(2, HW, NIMG), 256, CONV_SMEM_FLOATS * 4>>>(x);
    attn_kernel<<<dim3(32, NSUB), 256, ASMEM>>>(out);
}

// round 15
// speedup vs baseline: 1.5253x; 1.0558x over previous
#include <cuda_runtime.h>
#include <cuda_fp16.h>

#define NIMG 8
#define CIN  128
#define HW   128
#define NSUB 32
#define PADD 72
#define PPLANE (PADD*PADD)

// channel-last fp16 hi/lo globals (zero-init -> padded borders are 0)
__device__ __align__(16) __half g_Qhi[(size_t)NSUB * 4096 * 64];
__device__ __align__(16) __half g_Qlo[(size_t)NSUB * 4096 * 64];
__device__ __align__(16) __half g_Khi[(size_t)NSUB * PPLANE * 64];
__device__ __align__(16) __half g_Klo[(size_t)NSUB * PPLANE * 64];
__device__ __align__(16) __half g_Vhi[(size_t)NSUB * PPLANE * 64];
__device__ __align__(16) float  g_Wt[128 * 192];

typedef unsigned long long u64;
typedef unsigned u32;

__device__ __forceinline__ u64 pk2(float a, float b) {
    u64 r; asm("mov.b64 %0, {%1, %2};" : "=l"(r) : "f"(a), "f"(b)); return r;
}
__device__ __forceinline__ void up2(u64 v, float& a, float& b) {
    asm("mov.b64 {%0, %1}, %2;" : "=f"(a), "=f"(b) : "l"(v));
}
__device__ __forceinline__ void fma2(u64& d, u64 a, u64 b) {
    asm("fma.rn.f32x2 %0, %1, %2, %3;" : "=l"(d) : "l"(a), "l"(b), "l"(d));
}
__device__ __forceinline__ void lds2(u64& a, u64& b, const float* p) {
    unsigned sp = (unsigned)__cvta_generic_to_shared(p);
    asm volatile("ld.shared.v2.b64 {%0, %1}, [%2];" : "=l"(a), "=l"(b) : "r"(sp));
}
__device__ __forceinline__ u32 smem_u32(const void* p) {
    u32 a;
    asm("{ .reg .u64 t; cvta.to.shared.u64 t, %1; cvt.u32.u64 %0, t; }" : "=r"(a) : "l"(p));
    return a;
}
__device__ __forceinline__ void ldsm4(u32* r, u32 a) {
    asm volatile("ldmatrix.sync.aligned.m8n8.x4.shared.b16 {%0,%1,%2,%3}, [%4];"
        : "=r"(r[0]), "=r"(r[1]), "=r"(r[2]), "=r"(r[3]) : "r"(a));
}
__device__ __forceinline__ void ldsm4t(u32* r, u32 a) {
    asm volatile("ldmatrix.sync.aligned.m8n8.x4.trans.shared.b16 {%0,%1,%2,%3}, [%4];"
        : "=r"(r[0]), "=r"(r[1]), "=r"(r[2]), "=r"(r[3]) : "r"(a));
}
__device__ __forceinline__ void mma16816(float* d, const u32* a, u32 b0, u32 b1) {
    asm volatile("mma.sync.aligned.m16n8k16.row.col.f32.f16.f16.f32 "
        "{%0,%1,%2,%3}, {%4,%5,%6,%7}, {%8,%9}, {%0,%1,%2,%3};"
        : "+f"(d[0]), "+f"(d[1]), "+f"(d[2]), "+f"(d[3])
        : "r"(a[0]), "r"(a[1]), "r"(a[2]), "r"(a[3]), "r"(b0), "r"(b1));
}
__device__ __forceinline__ u32 packh2(float lo, float hi) {
    u32 r; asm("cvt.rn.f16x2.f32 %0, %1, %2;" : "=r"(r) : "f"(hi), "f"(lo));
    return r;
}
__device__ __forceinline__ float hresid(float x) {
    return x - __half2float(__float2half_rn(x));
}

// ---------------------------------------------------------------------------
__global__ void wt_kernel(const float* __restrict__ W1, const float* __restrict__ W2,
                          const float* __restrict__ W3)
{
    int i = blockIdx.x * 256 + threadIdx.x;
    if (i >= 192 * 128) return;
    int o = i >> 7, c = i & 127;
    const float* Wt = (o < 64) ? W1 : ((o < 128) ? W2 : W3);
    g_Wt[c * 192 + o] = Wt[(o & 63) * 128 + c];
}

// ---------------------------------------------------------------------------
// conv: round-7 GEMM core; epilogue bounces Q,K,V via smem and stores fp16
// channel-last (hi+lo for Q,K; hi only for V — V residual dropped, error
// budget ~2.8e-4 RMS, well under the 1e-3 threshold).
// ---------------------------------------------------------------------------
#define CONV_SMEM_FLOATS 8192
__global__ __launch_bounds__(256, 3) void conv_kernel(const float* __restrict__ x)
{
    extern __shared__ float sm[];
    float* xs = sm;
    const int tid = threadIdx.x;
    const int wh = blockIdx.x, h = blockIdx.y, n = blockIdx.z;
    const int w0 = wh * 64, w_t = tid & 15, oc_t = tid >> 4;

    const float* xbase = x + ((size_t)n * CIN) * HW * HW + (size_t)h * HW + w0;
    #pragma unroll
    for (int it = 0; it < 8; it++) {
        int i = it * 256 + tid;
        int c = i >> 4, w4 = (i & 15) << 2;
        *(float4*)&xs[c * 64 + w4] = *(const float4*)(xbase + (size_t)c * HW * HW + w4);
    }
    __syncthreads();

    u64 acc[12][2];
    #pragma unroll
    for (int j = 0; j < 12; j++) { acc[j][0] = 0ull; acc[j][1] = 0ull; }
    const float* wrow = g_Wt + 12 * oc_t;
    #pragma unroll 4
    for (int c = 0; c < 128; c++) {
        u64 xp0, xp1;
        lds2(xp0, xp1, &xs[c * 64 + 4 * w_t]);
        const float4 wa = __ldg((const float4*)(wrow + c * 192));
        const float4 wb = __ldg((const float4*)(wrow + c * 192 + 4));
        const float4 wc = __ldg((const float4*)(wrow + c * 192 + 8));
        float wv[12] = {wa.x, wa.y, wa.z, wa.w, wb.x, wb.y, wb.z, wb.w,
                        wc.x, wc.y, wc.z, wc.w};
        #pragma unroll
        for (int j = 0; j < 12; j++) {
            u64 s = pk2(wv[j], wv[j]);
            fma2(acc[j][0], s, xp0);
            fma2(acc[j][1], s, xp1);
        }
    }
    float ov[12][4];
    #pragma unroll
    for (int j = 0; j < 12; j++) {
        up2(acc[j][0], ov[j][0], ov[j][1]);
        up2(acc[j][1], ov[j][2], ov[j][3]);
    }

    const int sy = h >> 1, ph2 = (h & 1) * 2;
    float* vsm = sm;
    #pragma unroll 1
    for (int rnd = 0; rnd < 3; rnd++) {
        __syncthreads();
        #pragma unroll
        for (int j = 0; j < 12; j++) {
            int o = 12 * oc_t + j;
            if ((o >> 6) == rnd) {
                int oc = o & 63;
                #pragma unroll
                for (int jj = 0; jj < 4; jj++)
                    vsm[(4 * w_t + jj) * 68 + oc] = ov[j][jj];
            }
        }
        __syncthreads();
        #pragma unroll
        for (int it = 0; it < 4; it++) {
            int i = it * 256 + tid;           // (wl 64, c4 16)
            int c4 = i & 15, wl = i >> 4;
            float4 v = *(float4*)&vsm[wl * 68 + c4 * 4];
            uint2 hi;
            hi.x = packh2(v.x, v.y); hi.y = packh2(v.z, v.w);
            int w = w0 + wl, pw = w & 1, sx = w >> 1;
            int sub = n * 4 + ph2 + pw;
            if (rnd == 0) {
                size_t a = ((size_t)sub * 4096 + sy * 64 + sx) * 64 + c4 * 4;
                uint2 lo;
                lo.x = packh2(hresid(v.x), hresid(v.y));
                lo.y = packh2(hresid(v.z), hresid(v.w));
                *(uint2*)(g_Qhi + a) = hi;
                *(uint2*)(g_Qlo + a) = lo;
            } else if (rnd == 1) {
                size_t a = ((size_t)sub * PPLANE + (sy + 4) * PADD + sx + 4) * 64 + c4 * 4;
                uint2 lo;
                lo.x = packh2(hresid(v.x), hresid(v.y));
                lo.y = packh2(hresid(v.z), hresid(v.w));
                *(uint2*)(g_Khi + a) = hi;
                *(uint2*)(g_Klo + a) = lo;
            } else {
                size_t a = ((size_t)sub * PPLANE + (sy + 4) * PADD + sx + 4) * 64 + c4 * 4;
                *(uint2*)(g_Vhi + a) = hi;
            }
        }
    }
}

// ---------------------------------------------------------------------------
// attn: mma.sync flash pipeline. 256 thr, 1 CTA/SM, 176KB smem.
// smem: Q [128px][64ch] hi/lo (16KB ea), K [384pos][64ch] hi/lo (48KB ea),
// V hi [384pos][64ch] (48KB). Rows 128B, 16B-chunk XOR swizzle.
// O = P_hi . V_hi single combo (P/V residuals dropped; ~4e-4 RMS total).
// ---------------------------------------------------------------------------
#define SQ_HI 0
#define SQ_LO 16384
#define SK_HI 32768
#define SK_LO 81920
#define SV_HI 131072
#define ASMEM 180224

__global__ __launch_bounds__(256, 1) void attn_kernel(float* __restrict__ out)
{
    extern __shared__ char smc[];
    const u32 sb = smem_u32(smc);
    const int tid = threadIdx.x, lane = tid & 31, w = tid >> 5;
    const int tile = blockIdx.x, sub = blockIdx.y;
    const int byy = tile >> 3, bx = tile & 7;

    // ---- stage Q ----
    #pragma unroll
    for (int it = 0; it < 4; it++) {
        int i = it * 256 + tid;               // (r 128, ck 8)
        int r = i >> 3, ck = i & 7;
        int sy = byy * 16 + (r >> 3), sx = bx * 8 + (r & 7);
        size_t ga = ((size_t)sub * 4096 + sy * 64 + sx) * 64 + ck * 8;
        u32 off = r * 128 + ((ck ^ (r & 7)) << 4);
        *(uint4*)(smc + SQ_HI + off) = *(const uint4*)(g_Qhi + ga);
        *(uint4*)(smc + SQ_LO + off) = *(const uint4*)(g_Qlo + ga);
    }
    // ---- stage K,V ----
    #pragma unroll
    for (int it = 0; it < 12; it++) {
        int i = it * 256 + tid;               // (pos 384, ck 8)
        int pos = i >> 3, ck = i & 7;
        int py = byy * 16 + (pos >> 4), px = bx * 8 + (pos & 15);
        size_t ga = ((size_t)sub * PPLANE + py * PADD + px) * 64 + ck * 8;
        u32 off = pos * 128 + ((ck ^ (pos & 7)) << 4);
        *(uint4*)(smc + SK_HI + off) = *(const uint4*)(g_Khi + ga);
        *(uint4*)(smc + SK_LO + off) = *(const uint4*)(g_Klo + ga);
        *(uint4*)(smc + SV_HI + off) = *(const uint4*)(g_Vhi + ga);
    }
    __syncthreads();

    // ---- A fragments: Q rows 16w..16w+15, 4 k-steps ----
    u32 ah[4][4], al[4][4];
    {
        int ar = 16 * w + (lane & 15);
        #pragma unroll
        for (int t = 0; t < 4; t++) {
            u32 ck = 2 * t + (lane >> 4);
            u32 off = ar * 128 + ((ck ^ (ar & 7)) << 4);
            ldsm4(ah[t], sb + SQ_HI + off);
            ldsm4(al[t], sb + SQ_LO + off);
        }
    }

    const int g = lane >> 2, tg = lane & 3;
    float m0 = -1e30f, m1 = -1e30f, s0 = 0.f, s1 = 0.f;
    float o[8][4];
    #pragma unroll
    for (int nb = 0; nb < 8; nb++)
        #pragma unroll
        for (int j = 0; j < 4; j++) o[nb][j] = 0.f;

    const int cb0 = w >> 1;
    #pragma unroll 1
    for (int ci = 0; ci < 3; ci++) {
        const int cb = cb0 + ci;

        // ---- S = Q.K^T over 64-pos chunk (3 hi/lo combos) ----
        float sacc[8][4];
        #pragma unroll
        for (int nb = 0; nb < 8; nb++)
            #pragma unroll
            for (int j = 0; j < 4; j++) sacc[nb][j] = 0.f;

        #pragma unroll
        for (int t = 0; t < 4; t++) {
            int rb = 64 * cb + ((lane >> 4) << 3) + (lane & 7);
            u32 ck = 2 * t + ((lane >> 3) & 1);
            u32 bh[4][4];
            #pragma unroll
            for (int u = 0; u < 4; u++) {
                int r2 = rb + 16 * u;
                ldsm4(bh[u], sb + SK_HI + r2 * 128 + ((ck ^ (r2 & 7)) << 4));
            }
            #pragma unroll
            for (int nb = 0; nb < 8; nb++) {
                mma16816(sacc[nb], ah[t], bh[nb >> 1][(nb & 1) * 2], bh[nb >> 1][(nb & 1) * 2 + 1]);
                mma16816(sacc[nb], al[t], bh[nb >> 1][(nb & 1) * 2], bh[nb >> 1][(nb & 1) * 2 + 1]);
            }
            #pragma unroll
            for (int u = 0; u < 4; u++) {
                int r2 = rb + 16 * u;
                ldsm4(bh[u], sb + SK_LO + r2 * 128 + ((ck ^ (r2 & 7)) << 4));
            }
            #pragma unroll
            for (int nb = 0; nb < 8; nb++)
                mma16816(sacc[nb], ah[t], bh[nb >> 1][(nb & 1) * 2], bh[nb >> 1][(nb & 1) * 2 + 1]);
        }

        // ---- mask (rows ty=2w,2w+1; cols tx=g) ----
        #pragma unroll
        for (int nb = 0; nb < 8; nb++) {
            int hy = 4 * cb + (nb >> 1);
            int hx0 = (nb & 1) * 8 + tg * 2;
            bool y0 = (unsigned)(hy - 2 * w) <= 8u;
            bool y1 = (unsigned)(hy - 2 * w - 1) <= 8u;
            bool x0 = (unsigned)(hx0 - g) <= 8u;
            bool x1 = (unsigned)(hx0 + 1 - g) <= 8u;
            if (!(y0 && x0)) sacc[nb][0] = -1e30f;
            if (!(y0 && x1)) sacc[nb][1] = -1e30f;
            if (!(y1 && x0)) sacc[nb][2] = -1e30f;
            if (!(y1 && x1)) sacc[nb][3] = -1e30f;
        }

        // ---- running max + rescale ----
        float mn0 = -1e30f, mn1 = -1e30f;
        #pragma unroll
        for (int nb = 0; nb < 8; nb++) {
            mn0 = fmaxf(mn0, fmaxf(sacc[nb][0], sacc[nb][1]));
            mn1 = fmaxf(mn1, fmaxf(sacc[nb][2], sacc[nb][3]));
        }
        mn0 = fmaxf(mn0, __shfl_xor_sync(0xffffffffu, mn0, 1));
        mn0 = fmaxf(mn0, __shfl_xor_sync(0xffffffffu, mn0, 2));
        mn1 = fmaxf(mn1, __shfl_xor_sync(0xffffffffu, mn1, 1));
        mn1 = fmaxf(mn1, __shfl_xor_sync(0xffffffffu, mn1, 2));
        float nm0 = fmaxf(m0, mn0), nm1 = fmaxf(m1, mn1);
        float sc0 = __expf(m0 - nm0), sc1 = __expf(m1 - nm1);
        m0 = nm0; m1 = nm1;
        s0 *= sc0; s1 *= sc1;
        #pragma unroll
        for (int nb = 0; nb < 8; nb++) {
            o[nb][0] *= sc0; o[nb][1] *= sc0;
            o[nb][2] *= sc1; o[nb][3] *= sc1;
        }

        // ---- P = exp(s-m) as fp16 A fragments (hi only) ----
        u32 pa[4][4];
        #pragma unroll
        for (int st = 0; st < 4; st++) {
            float q0 = __expf(sacc[2 * st][0] - m0), q1 = __expf(sacc[2 * st][1] - m0);
            float q2 = __expf(sacc[2 * st][2] - m1), q3 = __expf(sacc[2 * st][3] - m1);
            float r0 = __expf(sacc[2 * st + 1][0] - m0), r1 = __expf(sacc[2 * st + 1][1] - m0);
            float r2 = __expf(sacc[2 * st + 1][2] - m1), r3 = __expf(sacc[2 * st + 1][3] - m1);
            s0 += q0 + q1 + r0 + r1;
            s1 += q2 + q3 + r2 + r3;
            pa[st][0] = packh2(q0, q1); pa[st][1] = packh2(q2, q3);
            pa[st][2] = packh2(r0, r1); pa[st][3] = packh2(r2, r3);
        }

        // ---- O += P.V (single combo) ----
        #pragma unroll
        for (int st = 0; st < 4; st++) {
            int row = 64 * cb + 16 * st + ((lane >> 3) & 1) * 8 + (lane & 7);
            u32 bv[4][4];
            #pragma unroll
            for (int q = 0; q < 4; q++) {
                u32 ck = 2 * q + (lane >> 4);
                ldsm4t(bv[q], sb + SV_HI + row * 128 + ((ck ^ (row & 7)) << 4));
            }
            #pragma unroll
            for (int nb = 0; nb < 8; nb++)
                mma16816(o[nb], pa[st], bv[nb >> 1][(nb & 1) * 2], bv[nb >> 1][(nb & 1) * 2 + 1]);
        }
    }

    // ---- normalize ----
    s0 += __shfl_xor_sync(0xffffffffu, s0, 1);
    s0 += __shfl_xor_sync(0xffffffffu, s0, 2);
    s1 += __shfl_xor_sync(0xffffffffu, s1, 1);
    s1 += __shfl_xor_sync(0xffffffffu, s1, 2);
    float i0 = __fdividef(1.f, s0), i1 = __fdividef(1.f, s1);
    #pragma unroll
    for (int nb = 0; nb < 8; nb++) {
        o[nb][0] *= i0; o[nb][1] *= i0;
        o[nb][2] *= i1; o[nb][3] *= i1;
    }

    __syncthreads();                      // all smem operand reads done
    float* ob = (float*)smc;              // [128px][68] f32 bounce
    {
        int r0 = 16 * w + g, r1 = r0 + 8;
        #pragma unroll
        for (int nb = 0; nb < 8; nb++) {
            *(float2*)&ob[r0 * 68 + 8 * nb + tg * 2] = make_float2(o[nb][0], o[nb][1]);
            *(float2*)&ob[r1 * 68 + 8 * nb + tg * 2] = make_float2(o[nb][2], o[nb][3]);
        }
    }
    __syncthreads();

    const int nimg = sub >> 2;
    const int ph = (sub >> 1) & 1;
    const int pw = sub & 1;
    #pragma unroll
    for (int it = 0; it < 32; it++) {
        int i = it * 256 + tid;           // (tyy 16, c 64, txx 8)
        int txx = i & 7, c = (i >> 3) & 63, tyy = i >> 9;
        float val = ob[(tyy * 8 + txx) * 68 + c];
        int hh = 2 * (byy * 16 + tyy) + ph;
        int ww = 2 * (bx * 8 + txx) + pw;
        out[((size_t)(nimg * 64 + c)) * (HW * HW) + hh * HW + ww] = val;
    }
}

// ---------------------------------------------------------------------------
extern "C" void kernel_launch(void* const* d_in, const int* in_sizes, int n_in,
                              void* d_out, int out_size) {
    const float* x  = (const float*)d_in[0];
    const float* W1 = (const float*)d_in[1];
    const float* W2 = (const float*)d_in[2];
    const float* W3 = (const float*)d_in[3];
    float* out = (float*)d_out;
    (void)in_sizes; (void)n_in; (void)out_size;

    cudaFuncSetAttribute(attn_kernel, cudaFuncAttributeMaxDynamicSharedMemorySize,
                         ASMEM);

    wt_kernel<<<96, 256>>>(W1, W2, W3);
    conv_kernel<<<dim3(2, HW, NIMG), 256, CONV_SMEM_FLOATS * 4>>>(x);
    attn_kernel<<<dim3(32, NSUB), 256, ASMEM>>>(out);
}

// round 16
// speedup vs baseline: 2.9234x; 1.9167x over previous
#include <cuda_runtime.h>
#include <cuda_fp16.h>

#define NIMG 8
#define CIN  128
#define HW   128
#define NSUB 32
#define PADD 72
#define PPLANE (PADD*PADD)

// channel-last fp16 hi/lo globals (zero-init -> padded borders are 0)
__device__ __align__(16) __half g_Qhi[(size_t)NSUB * 4096 * 64];
__device__ __align__(16) __half g_Qlo[(size_t)NSUB * 4096 * 64];
__device__ __align__(16) __half g_Khi[(size_t)NSUB * PPLANE * 64];
__device__ __align__(16) __half g_Klo[(size_t)NSUB * PPLANE * 64];
__device__ __align__(16) __half g_Vhi[(size_t)NSUB * PPLANE * 64];
__device__ __align__(16) __half g_Whi[192 * 128];   // [o][c] fp16 hi
__device__ __align__(16) __half g_Wlo[192 * 128];   // [o][c] fp16 residual

typedef unsigned long long u64;
typedef unsigned u32;

__device__ __forceinline__ u32 smem_u32(const void* p) {
    u32 a;
    asm("{ .reg .u64 t; cvta.to.shared.u64 t, %1; cvt.u32.u64 %0, t; }" : "=r"(a) : "l"(p));
    return a;
}
__device__ __forceinline__ void ldsm4(u32* r, u32 a) {
    asm volatile("ldmatrix.sync.aligned.m8n8.x4.shared.b16 {%0,%1,%2,%3}, [%4];"
        : "=r"(r[0]), "=r"(r[1]), "=r"(r[2]), "=r"(r[3]) : "r"(a));
}
__device__ __forceinline__ void ldsm4t(u32* r, u32 a) {
    asm volatile("ldmatrix.sync.aligned.m8n8.x4.trans.shared.b16 {%0,%1,%2,%3}, [%4];"
        : "=r"(r[0]), "=r"(r[1]), "=r"(r[2]), "=r"(r[3]) : "r"(a));
}
__device__ __forceinline__ void mma16816(float* d, const u32* a, u32 b0, u32 b1) {
    asm volatile("mma.sync.aligned.m16n8k16.row.col.f32.f16.f16.f32 "
        "{%0,%1,%2,%3}, {%4,%5,%6,%7}, {%8,%9}, {%0,%1,%2,%3};"
        : "+f"(d[0]), "+f"(d[1]), "+f"(d[2]), "+f"(d[3])
        : "r"(a[0]), "r"(a[1]), "r"(a[2]), "r"(a[3]), "r"(b0), "r"(b1));
}
__device__ __forceinline__ u32 packh2(float lo, float hi) {
    u32 r; asm("cvt.rn.f16x2.f32 %0, %1, %2;" : "=r"(r) : "f"(hi), "f"(lo));
    return r;
}
__device__ __forceinline__ float hresid(float x) {
    return x - __half2float(__float2half_rn(x));
}

// ---------------------------------------------------------------------------
// Kernel 0: W -> fp16 hi/lo in [o][c] layout
// ---------------------------------------------------------------------------
__global__ void wt_kernel(const float* __restrict__ W1, const float* __restrict__ W2,
                          const float* __restrict__ W3)
{
    int i = blockIdx.x * 256 + threadIdx.x;
    if (i >= 192 * 128) return;
    int o = i >> 7, c = i & 127;
    const float* Wt = (o < 64) ? W1 : ((o < 128) ? W2 : W3);
    float v = Wt[(o & 63) * 128 + c];
    g_Whi[o * 128 + c] = __float2half_rn(v);
    g_Wlo[o * 128 + c] = __float2half_rn(hresid(v));
}

// ---------------------------------------------------------------------------
// Kernel 1: 1x1 convs via mma.sync. CTA = (h, n): one image row (128 px) x
// 192 oc. 256 thr, 1 CTA/SM.
// smem: x hi/lo [128c][128px] fp16 (32KB ea), W hi/lo [192oc][128c] (48KB ea)
//       = 160KB; all rows 256B, 16B-chunk XOR swizzle (ck ^= row&7).
// Warp w = px rows 16w..16w+15, all 192 oc; 3 combos (xh*Wh, xl*Wh, xh*Wl).
// A-frags from x via ldsm4t (validated V pattern), B-frags from W via ldsm4
// (validated K pattern). Epilogue: bounce f32 [128px][196], then the proven
// parity/hi-lo scatter to g_Q/g_K/g_V.
// ---------------------------------------------------------------------------
#define CX_HI 0
#define CX_LO 32768
#define CW_HI 65536
#define CW_LO 114688
#define CSMEM 163840

__global__ __launch_bounds__(256, 1) void conv_kernel(const float* __restrict__ x)
{
    extern __shared__ char smc[];
    const u32 sb = smem_u32(smc);
    const int tid = threadIdx.x, lane = tid & 31, w = tid >> 5;
    const int h = blockIdx.x, n = blockIdx.y;

    // ---- stage x[n][*][h][*] -> fp16 hi/lo [c][px] swizzled ----------------
    const float* xbase = x + ((size_t)n * CIN) * (HW * HW) + (size_t)h * HW;
    #pragma unroll
    for (int it = 0; it < 16; it++) {
        int i = it * 256 + tid;               // 4096 float4: (c 64.. wait c 128, w4 32)
        int c = i >> 5, w4 = (i & 31) << 2;
        float4 v = *(const float4*)(xbase + (size_t)c * (HW * HW) + w4);
        uint2 hi, lo;
        hi.x = packh2(v.x, v.y); hi.y = packh2(v.z, v.w);
        lo.x = packh2(hresid(v.x), hresid(v.y));
        lo.y = packh2(hresid(v.z), hresid(v.w));
        int ck = (i & 31) >> 1;               // 16B chunk (8 px)
        u32 off = c * 256 + ((ck ^ (c & 7)) << 4) + (i & 1) * 8;
        *(uint2*)(smc + CX_HI + off) = hi;
        *(uint2*)(smc + CX_LO + off) = lo;
    }
    // ---- stage W hi/lo [o][c] swizzled -------------------------------------
    #pragma unroll
    for (int it = 0; it < 12; it++) {
        int i = it * 256 + tid;               // 3072 uint4: (o 192, ck 16)
        int o = i >> 4, ck = i & 15;
        u32 off = o * 256 + ((ck ^ (o & 7)) << 4);
        *(uint4*)(smc + CW_HI + off) = *(const uint4*)(g_Whi + o * 128 + ck * 8);
        *(uint4*)(smc + CW_LO + off) = *(const uint4*)(g_Wlo + o * 128 + ck * 8);
    }
    __syncthreads();

    // ---- GEMM: 24 n-blocks (8 oc each) x 8 ksteps x 3 combos ---------------
    float oacc[24][4];
    #pragma unroll
    for (int nb = 0; nb < 24; nb++)
        #pragma unroll
        for (int j = 0; j < 4; j++) oacc[nb][j] = 0.f;

    #pragma unroll 1
    for (int t = 0; t < 8; t++) {
        // A-frags (x rows 16w..16w+15, k = 16t..16t+15) via ldsm4t on [c][px]
        u32 ah[4], al[4];
        {
            int c  = 16 * t + ((lane >> 4) << 3) + (lane & 7);
            int pc = 2 * w + ((lane >> 3) & 1);      // px 16B-chunk index
            u32 off = c * 256 + ((pc ^ (c & 7)) << 4);
            ldsm4t(ah, sb + CX_HI + off);
            ldsm4t(al, sb + CX_LO + off);
        }
        #pragma unroll
        for (int g6 = 0; g6 < 12; g6++) {           // 16-oc groups
            int row = g6 * 16 + ((lane >> 4) << 3) + (lane & 7);
            u32 ck = 2 * t + ((lane >> 3) & 1);
            u32 woff = row * 256 + ((ck ^ (row & 7)) << 4);
            u32 bh[4], bl[4];
            ldsm4(bh, sb + CW_HI + woff);
            ldsm4(bl, sb + CW_LO + woff);
            #pragma unroll
            for (int s = 0; s < 2; s++) {
                int nb = 2 * g6 + s;
                mma16816(oacc[nb], ah, bh[s * 2], bh[s * 2 + 1]);
                mma16816(oacc[nb], al, bh[s * 2], bh[s * 2 + 1]);
                mma16816(oacc[nb], ah, bl[s * 2], bl[s * 2 + 1]);
            }
        }
    }

    // ---- bounce accumulators to f32 [128px][196oc] -------------------------
    __syncthreads();
    float* ob = (float*)smc;
    {
        const int g = lane >> 2, tg = lane & 3;
        int r0 = 16 * w + g, r1 = r0 + 8;
        #pragma unroll
        for (int nb = 0; nb < 24; nb++) {
            *(float2*)&ob[r0 * 196 + nb * 8 + tg * 2] = make_float2(oacc[nb][0], oacc[nb][1]);
            *(float2*)&ob[r1 * 196 + nb * 8 + tg * 2] = make_float2(oacc[nb][2], oacc[nb][3]);
        }
    }
    __syncthreads();

    // ---- scatter: rnd 0=Q, 1=K, 2=V (parity subgrids, fp16 hi/lo) ----------
    const int sy = h >> 1, ph2 = (h & 1) * 2;
    #pragma unroll
    for (int rnd = 0; rnd < 3; rnd++) {
        #pragma unroll
        for (int it = 0; it < 8; it++) {
            int i = it * 256 + tid;            // 2048: (wl 128, c4 16)
            int c4 = i & 15, wl = i >> 4;
            float4 v = *(float4*)&ob[wl * 196 + rnd * 64 + c4 * 4];
            uint2 hi;
            hi.x = packh2(v.x, v.y); hi.y = packh2(v.z, v.w);
            int pw = wl & 1, sx = wl >> 1;
            int sub = n * 4 + ph2 + pw;
            if (rnd == 0) {
                size_t a = ((size_t)sub * 4096 + sy * 64 + sx) * 64 + c4 * 4;
                uint2 lo;
                lo.x = packh2(hresid(v.x), hresid(v.y));
                lo.y = packh2(hresid(v.z), hresid(v.w));
                *(uint2*)(g_Qhi + a) = hi;
                *(uint2*)(g_Qlo + a) = lo;
            } else if (rnd == 1) {
                size_t a = ((size_t)sub * PPLANE + (sy + 4) * PADD + sx + 4) * 64 + c4 * 4;
                uint2 lo;
                lo.x = packh2(hresid(v.x), hresid(v.y));
                lo.y = packh2(hresid(v.z), hresid(v.w));
                *(uint2*)(g_Khi + a) = hi;
                *(uint2*)(g_Klo + a) = lo;
            } else {
                size_t a = ((size_t)sub * PPLANE + (sy + 4) * PADD + sx + 4) * 64 + c4 * 4;
                *(uint2*)(g_Vhi + a) = hi;
            }
        }
    }
}

// ---------------------------------------------------------------------------
// Kernel 2: attn (round-15, unchanged). 256 thr, 176KB smem, 1 CTA/SM.
// ---------------------------------------------------------------------------
#define SQ_HI 0
#define SQ_LO 16384
#define SK_HI 32768
#define SK_LO 81920
#define SV_HI 131072
#define ASMEM 180224

__global__ __launch_bounds__(256, 1) void attn_kernel(float* __restrict__ out)
{
    extern __shared__ char smc[];
    const u32 sb = smem_u32(smc);
    const int tid = threadIdx.x, lane = tid & 31, w = tid >> 5;
    const int tile = blockIdx.x, sub = blockIdx.y;
    const int byy = tile >> 3, bx = tile & 7;

    #pragma unroll
    for (int it = 0; it < 4; it++) {
        int i = it * 256 + tid;
        int r = i >> 3, ck = i & 7;
        int sy = byy * 16 + (r >> 3), sx = bx * 8 + (r & 7);
        size_t ga = ((size_t)sub * 4096 + sy * 64 + sx) * 64 + ck * 8;
        u32 off = r * 128 + ((ck ^ (r & 7)) << 4);
        *(uint4*)(smc + SQ_HI + off) = *(const uint4*)(g_Qhi + ga);
        *(uint4*)(smc + SQ_LO + off) = *(const uint4*)(g_Qlo + ga);
    }
    #pragma unroll
    for (int it = 0; it < 12; it++) {
        int i = it * 256 + tid;
        int pos = i >> 3, ck = i & 7;
        int py = byy * 16 + (pos >> 4), px = bx * 8 + (pos & 15);
        size_t ga = ((size_t)sub * PPLANE + py * PADD + px) * 64 + ck * 8;
        u32 off = pos * 128 + ((ck ^ (pos & 7)) << 4);
        *(uint4*)(smc + SK_HI + off) = *(const uint4*)(g_Khi + ga);
        *(uint4*)(smc + SK_LO + off) = *(const uint4*)(g_Klo + ga);
        *(uint4*)(smc + SV_HI + off) = *(const uint4*)(g_Vhi + ga);
    }
    __syncthreads();

    u32 ah[4][4], al[4][4];
    {
        int ar = 16 * w + (lane & 15);
        #pragma unroll
        for (int t = 0; t < 4; t++) {
            u32 ck = 2 * t + (lane >> 4);
            u32 off = ar * 128 + ((ck ^ (ar & 7)) << 4);
            ldsm4(ah[t], sb + SQ_HI + off);
            ldsm4(al[t], sb + SQ_LO + off);
        }
    }

    const int g = lane >> 2, tg = lane & 3;
    float m0 = -1e30f, m1 = -1e30f, s0 = 0.f, s1 = 0.f;
    float o[8][4];
    #pragma unroll
    for (int nb = 0; nb < 8; nb++)
        #pragma unroll
        for (int j = 0; j < 4; j++) o[nb][j] = 0.f;

    const int cb0 = w >> 1;
    #pragma unroll 1
    for (int ci = 0; ci < 3; ci++) {
        const int cb = cb0 + ci;

        float sacc[8][4];
        #pragma unroll
        for (int nb = 0; nb < 8; nb++)
            #pragma unroll
            for (int j = 0; j < 4; j++) sacc[nb][j] = 0.f;

        #pragma unroll
        for (int t = 0; t < 4; t++) {
            int rb = 64 * cb + ((lane >> 4) << 3) + (lane & 7);
            u32 ck = 2 * t + ((lane >> 3) & 1);
            u32 bh[4][4];
            #pragma unroll
            for (int u = 0; u < 4; u++) {
                int r2 = rb + 16 * u;
                ldsm4(bh[u], sb + SK_HI + r2 * 128 + ((ck ^ (r2 & 7)) << 4));
            }
            #pragma unroll
            for (int nb = 0; nb < 8; nb++) {
                mma16816(sacc[nb], ah[t], bh[nb >> 1][(nb & 1) * 2], bh[nb >> 1][(nb & 1) * 2 + 1]);
                mma16816(sacc[nb], al[t], bh[nb >> 1][(nb & 1) * 2], bh[nb >> 1][(nb & 1) * 2 + 1]);
            }
            #pragma unroll
            for (int u = 0; u < 4; u++) {
                int r2 = rb + 16 * u;
                ldsm4(bh[u], sb + SK_LO + r2 * 128 + ((ck ^ (r2 & 7)) << 4));
            }
            #pragma unroll
            for (int nb = 0; nb < 8; nb++)
                mma16816(sacc[nb], ah[t], bh[nb >> 1][(nb & 1) * 2], bh[nb >> 1][(nb & 1) * 2 + 1]);
        }

        #pragma unroll
        for (int nb = 0; nb < 8; nb++) {
            int hy = 4 * cb + (nb >> 1);
            int hx0 = (nb & 1) * 8 + tg * 2;
            bool y0 = (unsigned)(hy - 2 * w) <= 8u;
            bool y1 = (unsigned)(hy - 2 * w - 1) <= 8u;
            bool x0 = (unsigned)(hx0 - g) <= 8u;
            bool x1 = (unsigned)(hx0 + 1 - g) <= 8u;
            if (!(y0 && x0)) sacc[nb][0] = -1e30f;
            if (!(y0 && x1)) sacc[nb][1] = -1e30f;
            if (!(y1 && x0)) sacc[nb][2] = -1e30f;
            if (!(y1 && x1)) sacc[nb][3] = -1e30f;
        }

        float mn0 = -1e30f, mn1 = -1e30f;
        #pragma unroll
        for (int nb = 0; nb < 8; nb++) {
            mn0 = fmaxf(mn0, fmaxf(sacc[nb][0], sacc[nb][1]));
            mn1 = fmaxf(mn1, fmaxf(sacc[nb][2], sacc[nb][3]));
        }
        mn0 = fmaxf(mn0, __shfl_xor_sync(0xffffffffu, mn0, 1));
        mn0 = fmaxf(mn0, __shfl_xor_sync(0xffffffffu, mn0, 2));
        mn1 = fmaxf(mn1, __shfl_xor_sync(0xffffffffu, mn1, 1));
        mn1 = fmaxf(mn1, __shfl_xor_sync(0xffffffffu, mn1, 2));
        float nm0 = fmaxf(m0, mn0), nm1 = fmaxf(m1, mn1);
        float sc0 = __expf(m0 - nm0), sc1 = __expf(m1 - nm1);
        m0 = nm0; m1 = nm1;
        s0 *= sc0; s1 *= sc1;
        #pragma unroll
        for (int nb = 0; nb < 8; nb++) {
            o[nb][0] *= sc0; o[nb][1] *= sc0;
            o[nb][2] *= sc1; o[nb][3] *= sc1;
        }

        u32 pa[4][4];
        #pragma unroll
        for (int st = 0; st < 4; st++) {
            float q0 = __expf(sacc[2 * st][0] - m0), q1 = __expf(sacc[2 * st][1] - m0);
            float q2 = __expf(sacc[2 * st][2] - m1), q3 = __expf(sacc[2 * st][3] - m1);
            float r0 = __expf(sacc[2 * st + 1][0] - m0), r1 = __expf(sacc[2 * st + 1][1] - m0);
            float r2 = __expf(sacc[2 * st + 1][2] - m1), r3 = __expf(sacc[2 * st + 1][3] - m1);
            s0 += q0 + q1 + r0 + r1;
            s1 += q2 + q3 + r2 + r3;
            pa[st][0] = packh2(q0, q1); pa[st][1] = packh2(q2, q3);
            pa[st][2] = packh2(r0, r1); pa[st][3] = packh2(r2, r3);
        }

        #pragma unroll
        for (int st = 0; st < 4; st++) {
            int row = 64 * cb + 16 * st + ((lane >> 3) & 1) * 8 + (lane & 7);
            u32 bv[4][4];
            #pragma unroll
            for (int q = 0; q < 4; q++) {
                u32 ck = 2 * q + (lane >> 4);
                ldsm4t(bv[q], sb + SV_HI + row * 128 + ((ck ^ (row & 7)) << 4));
            }
            #pragma unroll
            for (int nb = 0; nb < 8; nb++)
                mma16816(o[nb], pa[st], bv[nb >> 1][(nb & 1) * 2], bv[nb >> 1][(nb & 1) * 2 + 1]);
        }
    }

    s0 += __shfl_xor_sync(0xffffffffu, s0, 1);
    s0 += __shfl_xor_sync(0xffffffffu, s0, 2);
    s1 += __shfl_xor_sync(0xffffffffu, s1, 1);
    s1 += __shfl_xor_sync(0xffffffffu, s1, 2);
    float i0 = __fdividef(1.f, s0), i1 = __fdividef(1.f, s1);
    #pragma unroll
    for (int nb = 0; nb < 8; nb++) {
        o[nb][0] *= i0; o[nb][1] *= i0;
        o[nb][2] *= i1; o[nb][3] *= i1;
    }

    __syncthreads();
    float* ob = (float*)smc;
    {
        int r0 = 16 * w + g, r1 = r0 + 8;
        #pragma unroll
        for (int nb = 0; nb < 8; nb++) {
            *(float2*)&ob[r0 * 68 + 8 * nb + tg * 2] = make_float2(o[nb][0], o[nb][1]);
            *(float2*)&ob[r1 * 68 + 8 * nb + tg * 2] = make_float2(o[nb][2], o[nb][3]);
        }
    }
    __syncthreads();

    const int nimg = sub >> 2;
    const int ph = (sub >> 1) & 1;
    const int pw = sub & 1;
    #pragma unroll
    for (int it = 0; it < 32; it++) {
        int i = it * 256 + tid;
        int txx = i & 7, c = (i >> 3) & 63, tyy = i >> 9;
        float val = ob[(tyy * 8 + txx) * 68 + c];
        int hh = 2 * (byy * 16 + tyy) + ph;
        int ww = 2 * (bx * 8 + txx) + pw;
        out[((size_t)(nimg * 64 + c)) * (HW * HW) + hh * HW + ww] = val;
    }
}

// ---------------------------------------------------------------------------
extern "C" void kernel_launch(void* const* d_in, const int* in_sizes, int n_in,
                              void* d_out, int out_size) {
    const float* x  = (const float*)d_in[0];
    const float* W1 = (const float*)d_in[1];
    const float* W2 = (const float*)d_in[2];
    const float* W3 = (const float*)d_in[3];
    float* out = (float*)d_out;
    (void)in_sizes; (void)n_in; (void)out_size;

    cudaFuncSetAttribute(conv_kernel, cudaFuncAttributeMaxDynamicSharedMemorySize,
                         CSMEM);
    cudaFuncSetAttribute(attn_kernel, cudaFuncAttributeMaxDynamicSharedMemorySize,
                         ASMEM);

    wt_kernel<<<96, 256>>>(W1, W2, W3);
    conv_kernel<<<dim3(HW, NIMG), 256, CSMEM>>>(x);
    attn_kernel<<<dim3(32, NSUB), 256, ASMEM>>>(out);
}

// round 17
// speedup vs baseline: 2.9690x; 1.0156x over previous
#include <cuda_runtime.h>
#include <cuda_fp16.h>

#define NIMG 8
#define CIN  128
#define HW   128
#define NSUB 32
#define PADD 72
#define PPLANE (PADD*PADD)

// channel-last fp16 hi/lo globals (zero-init -> padded borders are 0)
__device__ __align__(16) __half g_Qhi[(size_t)NSUB * 4096 * 64];
__device__ __align__(16) __half g_Qlo[(size_t)NSUB * 4096 * 64];
__device__ __align__(16) __half g_Khi[(size_t)NSUB * PPLANE * 64];
__device__ __align__(16) __half g_Klo[(size_t)NSUB * PPLANE * 64];
__device__ __align__(16) __half g_Vhi[(size_t)NSUB * PPLANE * 64];

typedef unsigned long long u64;
typedef unsigned u32;

__device__ __forceinline__ u32 smem_u32(const void* p) {
    u32 a;
    asm("{ .reg .u64 t; cvta.to.shared.u64 t, %1; cvt.u32.u64 %0, t; }" : "=r"(a) : "l"(p));
    return a;
}
__device__ __forceinline__ void ldsm4(u32* r, u32 a) {
    asm volatile("ldmatrix.sync.aligned.m8n8.x4.shared.b16 {%0,%1,%2,%3}, [%4];"
        : "=r"(r[0]), "=r"(r[1]), "=r"(r[2]), "=r"(r[3]) : "r"(a));
}
__device__ __forceinline__ void ldsm4t(u32* r, u32 a) {
    asm volatile("ldmatrix.sync.aligned.m8n8.x4.trans.shared.b16 {%0,%1,%2,%3}, [%4];"
        : "=r"(r[0]), "=r"(r[1]), "=r"(r[2]), "=r"(r[3]) : "r"(a));
}
__device__ __forceinline__ void mma16816(float* d, const u32* a, u32 b0, u32 b1) {
    asm volatile("mma.sync.aligned.m16n8k16.row.col.f32.f16.f16.f32 "
        "{%0,%1,%2,%3}, {%4,%5,%6,%7}, {%8,%9}, {%0,%1,%2,%3};"
        : "+f"(d[0]), "+f"(d[1]), "+f"(d[2]), "+f"(d[3])
        : "r"(a[0]), "r"(a[1]), "r"(a[2]), "r"(a[3]), "r"(b0), "r"(b1));
}
__device__ __forceinline__ u32 packh2(float lo, float hi) {
    u32 r; asm("cvt.rn.f16x2.f32 %0, %1, %2;" : "=r"(r) : "f"(hi), "f"(lo));
    return r;
}
__device__ __forceinline__ float hresid(float x) {
    return x - __half2float(__float2half_rn(x));
}

// ---------------------------------------------------------------------------
// Kernel 1: 1x1 convs via mma.sync. CTA = (h, n). 256 thr, 1 CTA/SM.
// smem: x hi/lo [128c][128px] (32KB ea), W hi/lo [192oc][128c] (48KB ea).
// W staged directly from fp32 W1/W2/W3 (hi/lo conversion in staging loop —
// wt_kernel removed). Rows 256B, 16B-chunk XOR swizzle (ck ^= row&7).
// ---------------------------------------------------------------------------
#define CX_HI 0
#define CX_LO 32768
#define CW_HI 65536
#define CW_LO 114688
#define CSMEM 163840

__global__ __launch_bounds__(256, 1) void conv_kernel(
    const float* __restrict__ x,
    const float* __restrict__ W1,
    const float* __restrict__ W2,
    const float* __restrict__ W3)
{
    extern __shared__ char smc[];
    const u32 sb = smem_u32(smc);
    const int tid = threadIdx.x, lane = tid & 31, w = tid >> 5;
    const int h = blockIdx.x, n = blockIdx.y;

    // ---- stage x[n][*][h][*] -> fp16 hi/lo [c][px] swizzled ----------------
    const float* xbase = x + ((size_t)n * CIN) * (HW * HW) + (size_t)h * HW;
    #pragma unroll
    for (int it = 0; it < 16; it++) {
        int i = it * 256 + tid;               // 4096 float4: (c 128, w4 32)
        int c = i >> 5, w4 = (i & 31) << 2;
        float4 v = *(const float4*)(xbase + (size_t)c * (HW * HW) + w4);
        uint2 hi, lo;
        hi.x = packh2(v.x, v.y); hi.y = packh2(v.z, v.w);
        lo.x = packh2(hresid(v.x), hresid(v.y));
        lo.y = packh2(hresid(v.z), hresid(v.w));
        int ck = (i & 31) >> 1;
        u32 off = c * 256 + ((ck ^ (c & 7)) << 4) + (i & 1) * 8;
        *(uint2*)(smc + CX_HI + off) = hi;
        *(uint2*)(smc + CX_LO + off) = lo;
    }
    // ---- stage W fp32 -> fp16 hi/lo [o][c] swizzled ------------------------
    #pragma unroll
    for (int it = 0; it < 12; it++) {
        int i = it * 256 + tid;               // 3072 chunks: (o 192, ck 16)
        int o = i >> 4, ck = i & 15;
        const float* Wsrc = (o < 64) ? W1 : ((o < 128) ? W2 : W3);
        const float* wr = Wsrc + (size_t)(o & 63) * 128 + ck * 8;
        float4 a = *(const float4*)(wr);
        float4 b = *(const float4*)(wr + 4);
        uint4 hi, lo;
        hi.x = packh2(a.x, a.y); hi.y = packh2(a.z, a.w);
        hi.z = packh2(b.x, b.y); hi.w = packh2(b.z, b.w);
        lo.x = packh2(hresid(a.x), hresid(a.y));
        lo.y = packh2(hresid(a.z), hresid(a.w));
        lo.z = packh2(hresid(b.x), hresid(b.y));
        lo.w = packh2(hresid(b.z), hresid(b.w));
        u32 off = o * 256 + ((ck ^ (o & 7)) << 4);
        *(uint4*)(smc + CW_HI + off) = hi;
        *(uint4*)(smc + CW_LO + off) = lo;
    }
    __syncthreads();

    // ---- GEMM: 24 n-blocks (8 oc each) x 8 ksteps x 3 combos ---------------
    float oacc[24][4];
    #pragma unroll
    for (int nb = 0; nb < 24; nb++)
        #pragma unroll
        for (int j = 0; j < 4; j++) oacc[nb][j] = 0.f;

    #pragma unroll 1
    for (int t = 0; t < 8; t++) {
        u32 ah[4], al[4];
        {
            int c  = 16 * t + ((lane >> 4) << 3) + (lane & 7);
            int pc = 2 * w + ((lane >> 3) & 1);
            u32 off = c * 256 + ((pc ^ (c & 7)) << 4);
            ldsm4t(ah, sb + CX_HI + off);
            ldsm4t(al, sb + CX_LO + off);
        }
        #pragma unroll
        for (int g6 = 0; g6 < 12; g6++) {
            int row = g6 * 16 + ((lane >> 4) << 3) + (lane & 7);
            u32 ck = 2 * t + ((lane >> 3) & 1);
            u32 woff = row * 256 + ((ck ^ (row & 7)) << 4);
            u32 bh[4], bl[4];
            ldsm4(bh, sb + CW_HI + woff);
            ldsm4(bl, sb + CW_LO + woff);
            #pragma unroll
            for (int s = 0; s < 2; s++) {
                int nb = 2 * g6 + s;
                mma16816(oacc[nb], ah, bh[s * 2], bh[s * 2 + 1]);
                mma16816(oacc[nb], al, bh[s * 2], bh[s * 2 + 1]);
                mma16816(oacc[nb], ah, bl[s * 2], bl[s * 2 + 1]);
            }
        }
    }

    // ---- bounce accumulators to f32 [128px][196oc] -------------------------
    __syncthreads();
    float* ob = (float*)smc;
    {
        const int g = lane >> 2, tg = lane & 3;
        int r0 = 16 * w + g, r1 = r0 + 8;
        #pragma unroll
        for (int nb = 0; nb < 24; nb++) {
            *(float2*)&ob[r0 * 196 + nb * 8 + tg * 2] = make_float2(oacc[nb][0], oacc[nb][1]);
            *(float2*)&ob[r1 * 196 + nb * 8 + tg * 2] = make_float2(oacc[nb][2], oacc[nb][3]);
        }
    }
    __syncthreads();

    // ---- scatter: rnd 0=Q, 1=K, 2=V (parity subgrids, fp16 hi/lo) ----------
    const int sy = h >> 1, ph2 = (h & 1) * 2;
    #pragma unroll
    for (int rnd = 0; rnd < 3; rnd++) {
        #pragma unroll
        for (int it = 0; it < 8; it++) {
            int i = it * 256 + tid;            // 2048: (wl 128, c4 16)
            int c4 = i & 15, wl = i >> 4;
            float4 v = *(float4*)&ob[wl * 196 + rnd * 64 + c4 * 4];
            uint2 hi;
            hi.x = packh2(v.x, v.y); hi.y = packh2(v.z, v.w);
            int pw = wl & 1, sx = wl >> 1;
            int sub = n * 4 + ph2 + pw;
            if (rnd == 0) {
                size_t a = ((size_t)sub * 4096 + sy * 64 + sx) * 64 + c4 * 4;
                uint2 lo;
                lo.x = packh2(hresid(v.x), hresid(v.y));
                lo.y = packh2(hresid(v.z), hresid(v.w));
                *(uint2*)(g_Qhi + a) = hi;
                *(uint2*)(g_Qlo + a) = lo;
            } else if (rnd == 1) {
                size_t a = ((size_t)sub * PPLANE + (sy + 4) * PADD + sx + 4) * 64 + c4 * 4;
                uint2 lo;
                lo.x = packh2(hresid(v.x), hresid(v.y));
                lo.y = packh2(hresid(v.z), hresid(v.w));
                *(uint2*)(g_Khi + a) = hi;
                *(uint2*)(g_Klo + a) = lo;
            } else {
                size_t a = ((size_t)sub * PPLANE + (sy + 4) * PADD + sx + 4) * 64 + c4 * 4;
                *(uint2*)(g_Vhi + a) = hi;
            }
        }
    }
}

// ---------------------------------------------------------------------------
// Kernel 2: attn, exact-window flash loop. 256 thr, 176KB smem, 1 CTA/SM.
// Warp w owns query rows ty=2w,2w+1 (px rows 16w..16w+15). 5 iterations of
// 2 halo rows (32 pos) cover exactly hy in [2w, 2w+9] — no wasted rows
// (was 3x64 pos = 192; now 5x32 = 160).
// ---------------------------------------------------------------------------
#define SQ_HI 0
#define SQ_LO 16384
#define SK_HI 32768
#define SK_LO 81920
#define SV_HI 131072
#define ASMEM 180224

__global__ __launch_bounds__(256, 1) void attn_kernel(float* __restrict__ out)
{
    extern __shared__ char smc[];
    const u32 sb = smem_u32(smc);
    const int tid = threadIdx.x, lane = tid & 31, w = tid >> 5;
    const int tile = blockIdx.x, sub = blockIdx.y;
    const int byy = tile >> 3, bx = tile & 7;

    // ---- stage Q ----
    #pragma unroll
    for (int it = 0; it < 4; it++) {
        int i = it * 256 + tid;
        int r = i >> 3, ck = i & 7;
        int sy = byy * 16 + (r >> 3), sx = bx * 8 + (r & 7);
        size_t ga = ((size_t)sub * 4096 + sy * 64 + sx) * 64 + ck * 8;
        u32 off = r * 128 + ((ck ^ (r & 7)) << 4);
        *(uint4*)(smc + SQ_HI + off) = *(const uint4*)(g_Qhi + ga);
        *(uint4*)(smc + SQ_LO + off) = *(const uint4*)(g_Qlo + ga);
    }
    // ---- stage K,V ----
    #pragma unroll
    for (int it = 0; it < 12; it++) {
        int i = it * 256 + tid;
        int pos = i >> 3, ck = i & 7;
        int py = byy * 16 + (pos >> 4), px = bx * 8 + (pos & 15);
        size_t ga = ((size_t)sub * PPLANE + py * PADD + px) * 64 + ck * 8;
        u32 off = pos * 128 + ((ck ^ (pos & 7)) << 4);
        *(uint4*)(smc + SK_HI + off) = *(const uint4*)(g_Khi + ga);
        *(uint4*)(smc + SK_LO + off) = *(const uint4*)(g_Klo + ga);
        *(uint4*)(smc + SV_HI + off) = *(const uint4*)(g_Vhi + ga);
    }
    __syncthreads();

    // ---- A fragments: Q rows 16w..16w+15, 4 k-steps ----
    u32 ah[4][4], al[4][4];
    {
        int ar = 16 * w + (lane & 15);
        #pragma unroll
        for (int t = 0; t < 4; t++) {
            u32 ck = 2 * t + (lane >> 4);
            u32 off = ar * 128 + ((ck ^ (ar & 7)) << 4);
            ldsm4(ah[t], sb + SQ_HI + off);
            ldsm4(al[t], sb + SQ_LO + off);
        }
    }

    const int g = lane >> 2, tg = lane & 3;
    float m0 = -1e30f, m1 = -1e30f, s0 = 0.f, s1 = 0.f;
    float o[8][4];
    #pragma unroll
    for (int nb = 0; nb < 8; nb++)
        #pragma unroll
        for (int j = 0; j < 4; j++) o[nb][j] = 0.f;

    #pragma unroll 1
    for (int it5 = 0; it5 < 5; it5++) {
        const int pb = (2 * w + 2 * it5) * 16;   // position base (2 halo rows)

        // ---- S = Q.K^T over 32 positions (3 hi/lo combos) ----
        float sacc[4][4];
        #pragma unroll
        for (int nb = 0; nb < 4; nb++)
            #pragma unroll
            for (int j = 0; j < 4; j++) sacc[nb][j] = 0.f;

        #pragma unroll
        for (int t = 0; t < 4; t++) {
            int rb = pb + ((lane >> 4) << 3) + (lane & 7);
            u32 ck = 2 * t + ((lane >> 3) & 1);
            u32 bh[2][4];
            #pragma unroll
            for (int u = 0; u < 2; u++) {
                int r2 = rb + 16 * u;
                ldsm4(bh[u], sb + SK_HI + r2 * 128 + ((ck ^ (r2 & 7)) << 4));
            }
            #pragma unroll
            for (int nb = 0; nb < 4; nb++) {
                mma16816(sacc[nb], ah[t], bh[nb >> 1][(nb & 1) * 2], bh[nb >> 1][(nb & 1) * 2 + 1]);
                mma16816(sacc[nb], al[t], bh[nb >> 1][(nb & 1) * 2], bh[nb >> 1][(nb & 1) * 2 + 1]);
            }
            #pragma unroll
            for (int u = 0; u < 2; u++) {
                int r2 = rb + 16 * u;
                ldsm4(bh[u], sb + SK_LO + r2 * 128 + ((ck ^ (r2 & 7)) << 4));
            }
            #pragma unroll
            for (int nb = 0; nb < 4; nb++)
                mma16816(sacc[nb], ah[t], bh[nb >> 1][(nb & 1) * 2], bh[nb >> 1][(nb & 1) * 2 + 1]);
        }

        // ---- mask: dy relative to ty0=2w is 2*it5 + (nb>>1) ----
        #pragma unroll
        for (int nb = 0; nb < 4; nb++) {
            int dy = 2 * it5 + (nb >> 1);
            int hx0 = (nb & 1) * 8 + tg * 2;
            bool y0 = dy <= 8;
            bool y1 = (unsigned)(dy - 1) <= 8u;
            bool x0 = (unsigned)(hx0 - g) <= 8u;
            bool x1 = (unsigned)(hx0 + 1 - g) <= 8u;
            if (!(y0 && x0)) sacc[nb][0] = -1e30f;
            if (!(y0 && x1)) sacc[nb][1] = -1e30f;
            if (!(y1 && x0)) sacc[nb][2] = -1e30f;
            if (!(y1 && x1)) sacc[nb][3] = -1e30f;
        }

        // ---- running max + rescale ----
        float mn0 = -1e30f, mn1 = -1e30f;
        #pragma unroll
        for (int nb = 0; nb < 4; nb++) {
            mn0 = fmaxf(mn0, fmaxf(sacc[nb][0], sacc[nb][1]));
            mn1 = fmaxf(mn1, fmaxf(sacc[nb][2], sacc[nb][3]));
        }
        mn0 = fmaxf(mn0, __shfl_xor_sync(0xffffffffu, mn0, 1));
        mn0 = fmaxf(mn0, __shfl_xor_sync(0xffffffffu, mn0, 2));
        mn1 = fmaxf(mn1, __shfl_xor_sync(0xffffffffu, mn1, 1));
        mn1 = fmaxf(mn1, __shfl_xor_sync(0xffffffffu, mn1, 2));
        float nm0 = fmaxf(m0, mn0), nm1 = fmaxf(m1, mn1);
        float sc0 = __expf(m0 - nm0), sc1 = __expf(m1 - nm1);
        m0 = nm0; m1 = nm1;
        s0 *= sc0; s1 *= sc1;
        #pragma unroll
        for (int nb = 0; nb < 8; nb++) {
            o[nb][0] *= sc0; o[nb][1] *= sc0;
            o[nb][2] *= sc1; o[nb][3] *= sc1;
        }

        // ---- P = exp(s-m) as fp16 A fragments (2 k-steps of 16 pos) ----
        u32 pa[2][4];
        #pragma unroll
        for (int st = 0; st < 2; st++) {
            float q0 = __expf(sacc[2 * st][0] - m0), q1 = __expf(sacc[2 * st][1] - m0);
            float q2 = __expf(sacc[2 * st][2] - m1), q3 = __expf(sacc[2 * st][3] - m1);
            float r0 = __expf(sacc[2 * st + 1][0] - m0), r1 = __expf(sacc[2 * st + 1][1] - m0);
            float r2 = __expf(sacc[2 * st + 1][2] - m1), r3 = __expf(sacc[2 * st + 1][3] - m1);
            s0 += q0 + q1 + r0 + r1;
            s1 += q2 + q3 + r2 + r3;
            pa[st][0] = packh2(q0, q1); pa[st][1] = packh2(q2, q3);
            pa[st][2] = packh2(r0, r1); pa[st][3] = packh2(r2, r3);
        }

        // ---- O += P.V over these 32 positions ----
        #pragma unroll
        for (int st = 0; st < 2; st++) {
            int row = pb + 16 * st + ((lane >> 3) & 1) * 8 + (lane & 7);
            u32 bv[4][4];
            #pragma unroll
            for (int q = 0; q < 4; q++) {
                u32 ck = 2 * q + (lane >> 4);
                ldsm4t(bv[q], sb + SV_HI + row * 128 + ((ck ^ (row & 7)) << 4));
            }
            #pragma unroll
            for (int nb = 0; nb < 8; nb++)
                mma16816(o[nb], pa[st], bv[nb >> 1][(nb & 1) * 2], bv[nb >> 1][(nb & 1) * 2 + 1]);
        }
    }

    // ---- normalize ----
    s0 += __shfl_xor_sync(0xffffffffu, s0, 1);
    s0 += __shfl_xor_sync(0xffffffffu, s0, 2);
    s1 += __shfl_xor_sync(0xffffffffu, s1, 1);
    s1 += __shfl_xor_sync(0xffffffffu, s1, 2);
    float i0 = __fdividef(1.f, s0), i1 = __fdividef(1.f, s1);
    #pragma unroll
    for (int nb = 0; nb < 8; nb++) {
        o[nb][0] *= i0; o[nb][1] *= i0;
        o[nb][2] *= i1; o[nb][3] *= i1;
    }

    __syncthreads();
    float* ob = (float*)smc;
    {
        int r0 = 16 * w + g, r1 = r0 + 8;
        #pragma unroll
        for (int nb = 0; nb < 8; nb++) {
            *(float2*)&ob[r0 * 68 + 8 * nb + tg * 2] = make_float2(o[nb][0], o[nb][1]);
            *(float2*)&ob[r1 * 68 + 8 * nb + tg * 2] = make_float2(o[nb][2], o[nb][3]);
        }
    }
    __syncthreads();

    const int nimg = sub >> 2;
    const int ph = (sub >> 1) & 1;
    const int pw = sub & 1;
    #pragma unroll
    for (int it = 0; it < 32; it++) {
        int i = it * 256 + tid;
        int txx = i & 7, c = (i >> 3) & 63, tyy = i >> 9;
        float val = ob[(tyy * 8 + txx) * 68 + c];
        int hh = 2 * (byy * 16 + tyy) + ph;
        int ww = 2 * (bx * 8 + txx) + pw;
        out[((size_t)(nimg * 64 + c)) * (HW * HW) + hh * HW + ww] = val;
    }
}

// ---------------------------------------------------------------------------
extern "C" void kernel_launch(void* const* d_in, const int* in_sizes, int n_in,
                              void* d_out, int out_size) {
    const float* x  = (const float*)d_in[0];
    const float* W1 = (const float*)d_in[1];
    const float* W2 = (const float*)d_in[2];
    const float* W3 = (const float*)d_in[3];
    float* out = (float*)d_out;
    (void)in_sizes; (void)n_in; (void)out_size;

    cudaFuncSetAttribute(conv_kernel, cudaFuncAttributeMaxDynamicSharedMemorySize,
                         CSMEM);
    cudaFuncSetAttribute(attn_kernel, cudaFuncAttributeMaxDynamicSharedMemorySize,
                         ASMEM);

    conv_kernel<<<dim3(HW, NIMG), 256, CSMEM>>>(x, W1, W2, W3);
    attn_kernel<<<dim3(32, NSUB), 256, ASMEM>>>(out);
}